// round 10
// baseline (speedup 1.0000x reference)
#include <cuda_runtime.h>
#include <cuda_bf16.h>
#include <cuda_fp16.h>
#include <math.h>
#include <stdint.h>

// ---------------- problem constants ----------------
#define VMAX 50000
#define EMAX 600000
#define Dg   256
#define Kp   20     // kron projection dim
#define KPAD 32     // padded projection dim for tensor-core GEMM
#define OUTD 256

// ---------------- device scratch (static; no allocation allowed) ----------------
__device__ float    g_npj[(size_t)VMAX * KPAD];        // padded fp32, cols 20..31 = 0
__device__ uint32_t g_npjh[(size_t)VMAX * 16];         // fp16 pairs (k,k+1)
__device__ float    g_Wkp[(size_t)KPAD * Kp * OUTD];   // W' o-major: [k][o*20+a]
__device__ float    g_ad[VMAX];
__device__ float    g_as[VMAX];
__device__ __half   g_hv[(size_t)VMAX * Dg];           // fp16
__device__ __half   g_T[(size_t)VMAX * Kp * OUTD];     // fp16, o-major: [v][o*20+a]
__device__ int      g_deg[VMAX];
__device__ int      g_offs[VMAX + 1];
__device__ int      g_bsums[256];
__device__ int      g_cursor[VMAX];
__device__ int      g_eids[EMAX];
__device__ float    g_att[EMAX];
__device__ float    g_ctx[(size_t)VMAX * Dg];
__device__ float    g_kf[(size_t)VMAX * OUTD];
__device__ __half   g_gi[(size_t)VMAX * 3 * Dg];       // fp16
__device__ __half   g_gh[(size_t)VMAX * 3 * Dg];       // fp16
__device__ float    g_cat[(size_t)VMAX * (Dg + OUTD)];

// ---------------- helpers ----------------
__device__ __forceinline__ float warp_sum(float v) {
    #pragma unroll
    for (int o = 16; o; o >>= 1) v += __shfl_xor_sync(0xffffffffu, v, o);
    return v;
}
__device__ __forceinline__ float warp_max(float v) {
    #pragma unroll
    for (int o = 16; o; o >>= 1) v = fmaxf(v, __shfl_xor_sync(0xffffffffu, v, o));
    return v;
}
__device__ __forceinline__ uint32_t f2h2(float a, float b) {
    __half2 h = __floats2half2_rn(a, b);
    return *(uint32_t*)&h;
}
__device__ __forceinline__ void mma_f16(float* d, const uint32_t* a, const uint32_t* b) {
    asm volatile(
        "mma.sync.aligned.m16n8k16.row.col.f32.f16.f16.f32 "
        "{%0,%1,%2,%3}, {%4,%5,%6,%7}, {%8,%9}, {%0,%1,%2,%3};\n"
        : "+f"(d[0]), "+f"(d[1]), "+f"(d[2]), "+f"(d[3])
        : "r"(a[0]), "r"(a[1]), "r"(a[2]), "r"(a[3]), "r"(b[0]), "r"(b[1]));
}

// block (256 thr) LN stats over one value per thread
__device__ __forceinline__ void ln_stats_256(float v, float* mu, float* rs) {
    __shared__ float s1[8], s2[8];
    float a = v, b = v * v;
    a = warp_sum(a); b = warp_sum(b);
    int w = threadIdx.x >> 5, l = threadIdx.x & 31;
    if (l == 0) { s1[w] = a; s2[w] = b; }
    __syncthreads();
    if (w == 0) {
        a = (l < 8) ? s1[l] : 0.f;
        b = (l < 8) ? s2[l] : 0.f;
        #pragma unroll
        for (int o = 4; o; o >>= 1) { a += __shfl_xor_sync(0xffffffffu, a, o); b += __shfl_xor_sync(0xffffffffu, b, o); }
        if (l == 0) { s1[0] = a; s2[0] = b; }
    }
    __syncthreads();
    float m = s1[0] * (1.f / 256.f);
    float var = s2[0] * (1.f / 256.f) - m * m;
    *mu = m;
    *rs = rsqrtf(var + 1e-5f);
}

// ---------------- fused preamble: npj (+att partials)  ||  Wkp transpose  ||  dst histogram ----------------
#define HIST_BLOCKS 592
__global__ void __launch_bounds__(256)
k_pre(const float* __restrict__ nf, const float* __restrict__ Wp,
      const float* __restrict__ bp, const float* __restrict__ gp,
      const float* __restrict__ betap, const float* __restrict__ We,
      const float* __restrict__ Wk, const int* __restrict__ dst,
      float* npj, __half* npjh, float* ad, float* as_, float* Wkp, int* deg,
      int V, int E) {
    int nb_npj = (V + 7) / 8;
    int nb_wkp = (KPAD * Kp * OUTD) / 256;   // 640
    int bid = blockIdx.x;
    if (bid < nb_npj) {
        int warp = bid * 8 + (threadIdx.x >> 5);
        int lane = threadIdx.x & 31;
        if (warp >= V) return;
        const float* x = nf + (size_t)warp * Dg;
        float xr[8];
        #pragma unroll
        for (int j = 0; j < 8; j++) xr[j] = x[j * 32 + lane];
        float pa = 0.f, pb = 0.f;
        #pragma unroll
        for (int j = 0; j < 8; j++) { int i = j * 32 + lane; pa += xr[j] * We[i]; pb += xr[j] * We[Dg + i]; }
        pa = warp_sum(pa); pb = warp_sum(pb);
        if (lane == 0) { ad[warp] = pa; as_[warp] = pb; }
        float val = 0.f;
        for (int k = 0; k < Kp; k++) {
            float p = 0.f;
            #pragma unroll
            for (int j = 0; j < 8; j++) { int i = j * 32 + lane; p += xr[j] * Wp[i * Kp + k]; }
            p = warp_sum(p);
            p += bp[k];
            if (lane == k) val = p;
        }
        float c = (lane < Kp) ? val : 0.f;
        float s = warp_sum(c);
        float s2 = warp_sum(c * c);
        float mu = s / (float)Kp;
        float var = s2 / (float)Kp - mu * mu;
        float rs = rsqrtf(var + 1e-5f);
        float y = (lane < Kp) ? fmaxf((val - mu) * rs * gp[lane] + betap[lane], 0.f) : 0.f;
        npj[(size_t)warp * KPAD + lane] = y;
        npjh[(size_t)warp * KPAD + lane] = __float2half(y);
    } else if (bid < nb_npj + nb_wkp) {
        // Wkp o-major: Wkp[k][n'], n' = o*20 + a  -> T'[v][o*20+a]
        int idx = (bid - nb_npj) * 256 + threadIdx.x;
        int k = idx / (Kp * OUTD);
        int n = idx % (Kp * OUTD);
        int a = n % Kp, o = n / Kp;
        Wkp[idx] = (k < Kp) ? Wk[(size_t)(a * Kp + k) * OUTD + o] : 0.f;
    } else {
        int vb = bid - nb_npj - nb_wkp;
        int stride = HIST_BLOCKS * 256;
        for (int i = vb * 256 + threadIdx.x; i < E; i += stride)
            atomicAdd(&deg[dst[i]], 1);
    }
}

// ---------------- fast 3-phase exclusive scan ----------------
__global__ void k_scan_part(const int* __restrict__ deg, int* offs, int* bsums, int V) {
    __shared__ int ws[8];
    int tid = threadIdx.x;
    int idx = blockIdx.x * 256 + tid;
    int v = (idx < V) ? deg[idx] : 0;
    int lane = tid & 31, w = tid >> 5;
    int x = v;
    #pragma unroll
    for (int o = 1; o < 32; o <<= 1) { int y = __shfl_up_sync(0xffffffffu, x, o); if (lane >= o) x += y; }
    if (lane == 31) ws[w] = x;
    __syncthreads();
    if (w == 0) {
        int s = (lane < 8) ? ws[lane] : 0;
        #pragma unroll
        for (int o = 1; o < 8; o <<= 1) { int y = __shfl_up_sync(0xffffffffu, s, o); if (lane >= o) s += y; }
        if (lane < 8) ws[lane] = s;
    }
    __syncthreads();
    int base = (w > 0) ? ws[w - 1] : 0;
    if (idx < V) offs[idx] = base + x - v;
    if (tid == 255) bsums[blockIdx.x] = base + x;
}
__global__ void k_scan_mid(int* bsums, int nb) {
    __shared__ int ws[8];
    int tid = threadIdx.x;
    int v = (tid < nb) ? bsums[tid] : 0;
    int lane = tid & 31, w = tid >> 5;
    int x = v;
    #pragma unroll
    for (int o = 1; o < 32; o <<= 1) { int y = __shfl_up_sync(0xffffffffu, x, o); if (lane >= o) x += y; }
    if (lane == 31) ws[w] = x;
    __syncthreads();
    if (w == 0) {
        int s = (lane < 8) ? ws[lane] : 0;
        #pragma unroll
        for (int o = 1; o < 8; o <<= 1) { int y = __shfl_up_sync(0xffffffffu, s, o); if (lane >= o) s += y; }
        if (lane < 8) ws[lane] = s;
    }
    __syncthreads();
    int base = (w > 0) ? ws[w - 1] : 0;
    if (tid < nb) bsums[tid] = base + x - v;
}
__global__ void k_scan_apply(int* offs, int* cursor, const int* __restrict__ bsums, int V, int E) {
    int idx = blockIdx.x * 256 + threadIdx.x;
    if (idx < V) {
        int o = offs[idx] + bsums[blockIdx.x];
        offs[idx] = o;
        cursor[idx] = o;
    }
    if (idx == 0) offs[V] = E;
}

__global__ void k_scatter(const int* __restrict__ dst, int* cursor, int* eids, int E) {
    for (int i = blockIdx.x * blockDim.x + threadIdx.x; i < E; i += gridDim.x * blockDim.x) {
        int p = atomicAdd(&cursor[dst[i]], 1);
        eids[p] = i;
    }
}

// ---------------- fused edge kernel: attn (gather) || kron (tensor-core mma) ----------------
__global__ void __launch_bounds__(256)
k_edge(const int* __restrict__ src, const int* __restrict__ eids,
       const int* __restrict__ offs, const uint32_t* __restrict__ npjh2,
       const __half* __restrict__ T, const float* __restrict__ bk,
       const float* __restrict__ gk, const float* __restrict__ betak,
       const float* __restrict__ ad, const float* __restrict__ as_,
       const float* __restrict__ be, const __half* __restrict__ hv,
       float* __restrict__ att, float* __restrict__ ctx,
       float* __restrict__ kf, int V) {
    // kron smem (unused by attn blocks)
    __shared__ uint32_t Tsh2[256 * 17];     // [o][k2] packed (a,a+1), k2 0..15 (>=10 zero)
    __shared__ uint32_t As2[16 * 17];       // [k2][edge]
    __shared__ float bks[OUTD], gks[OUTD], bes[OUTD];
    __shared__ float redS[16][8], redQ[16][8];
    __shared__ float smu[16], srs[16];

    int nb_attn = (V + 7) / 8;
    int bid = blockIdx.x;
    int tid = threadIdx.x;
    int lane = tid & 31, w = tid >> 5;

    if (bid < nb_attn) {
        // ================= attention + context =================
        int node = bid * 8 + w;
        if (node >= V) return;
        int e0 = offs[node], e1 = offs[node + 1];
        float b = be[0];
        float advv = ad[node];
        float mx = -1e30f;
        for (int i = e0 + lane; i < e1; i += 32) {
            int e = eids[i];
            float lg = fmaxf(advv + as_[src[e]] + b, 0.f);
            att[i] = lg;
            mx = fmaxf(mx, lg);
        }
        mx = warp_max(mx);
        float sm = 0.f;
        for (int i = e0 + lane; i < e1; i += 32) {
            float ex = expf(att[i] - mx);
            att[i] = ex;
            sm += ex;
        }
        sm = warp_sum(sm);
        float inv = (sm > 0.f) ? 1.f / sm : 0.f;
        float c[8];
        #pragma unroll
        for (int j = 0; j < 8; j++) c[j] = 0.f;
        int nw = 0; float ww = 0.f;
        if (e0 < e1) { nw = src[eids[e0]]; ww = att[e0] * inv; }
        for (int i = e0; i < e1; i++) {
            int cs = nw; float cw = ww;
            if (i + 1 < e1) { nw = src[eids[i + 1]]; ww = att[i + 1] * inv; }
            const uint4* hp = (const uint4*)(hv + (size_t)cs * Dg) + lane;
            uint4 u = *hp;
            float2 f0 = __half22float2(*(__half2*)&u.x);
            float2 f1 = __half22float2(*(__half2*)&u.y);
            float2 f2 = __half22float2(*(__half2*)&u.z);
            float2 f3 = __half22float2(*(__half2*)&u.w);
            c[0] = fmaf(cw, f0.x, c[0]); c[1] = fmaf(cw, f0.y, c[1]);
            c[2] = fmaf(cw, f1.x, c[2]); c[3] = fmaf(cw, f1.y, c[3]);
            c[4] = fmaf(cw, f2.x, c[4]); c[5] = fmaf(cw, f2.y, c[5]);
            c[6] = fmaf(cw, f3.x, c[6]); c[7] = fmaf(cw, f3.y, c[7]);
        }
        float4 o0, o1;
        o0.x = fmaxf(c[0], 0.f); o0.y = fmaxf(c[1], 0.f);
        o0.z = fmaxf(c[2], 0.f); o0.w = fmaxf(c[3], 0.f);
        o1.x = fmaxf(c[4], 0.f); o1.y = fmaxf(c[5], 0.f);
        o1.z = fmaxf(c[6], 0.f); o1.w = fmaxf(c[7], 0.f);
        float4* cp = (float4*)(ctx + (size_t)node * Dg) + lane * 2;
        cp[0] = o0; cp[1] = o1;
        return;
    }

    // ================= kron branch via mma (16 edges / group) =================
    int d = bid - nb_attn;
    {
        const uint32_t* Tp = (const uint32_t*)T + (size_t)d * (Kp * OUTD / 2);  // 2560 words
        for (int i = tid; i < 256 * 16; i += 256) {
            int o = i >> 4, k2 = i & 15;
            Tsh2[o * 17 + k2] = (k2 < 10) ? Tp[o * 10 + k2] : 0u;
        }
    }
    bks[tid] = bk[tid];
    gks[tid] = gk[tid];
    bes[tid] = betak[tid];
    __syncthreads();

    int e0 = offs[d], e1 = offs[d + 1];
    int gid = lane >> 2, tid4 = lane & 3;
    int cb = w * 32;

    float kacc[4][2];
    #pragma unroll
    for (int nt = 0; nt < 4; nt++) { kacc[nt][0] = 0.f; kacc[nt][1] = 0.f; }

    for (int g0 = e0; g0 < e1; g0 += 16) {
        // stage A: P[16 edges][32 k] as packed pairs [k2][edge]
        {
            int el = tid >> 4, k2 = tid & 15;
            int ei = g0 + el;
            uint32_t v = 0;
            if (ei < e1) { int s = src[eids[ei]]; v = npjh2[(size_t)s * 16 + k2]; }
            As2[k2 * 17 + el] = v;
        }
        __syncthreads();

        float dd[4][4];
        #pragma unroll
        for (int nt = 0; nt < 4; nt++)
            #pragma unroll
            for (int q = 0; q < 4; q++) dd[nt][q] = 0.f;

        #pragma unroll
        for (int ks = 0; ks < 2; ks++) {
            uint32_t a[4];
            a[0] = As2[(ks * 8 + tid4) * 17 + gid];
            a[1] = As2[(ks * 8 + tid4) * 17 + gid + 8];
            a[2] = As2[(ks * 8 + tid4 + 4) * 17 + gid];
            a[3] = As2[(ks * 8 + tid4 + 4) * 17 + gid + 8];
            #pragma unroll
            for (int nt = 0; nt < 4; nt++) {
                int col = cb + nt * 8 + gid;
                uint32_t b[2];
                b[0] = Tsh2[col * 17 + ks * 8 + tid4];
                b[1] = Tsh2[col * 17 + ks * 8 + tid4 + 4];
                mma_f16(dd[nt], a, b);
            }
        }

        // add bias; per-row partial stats (rows gid and gid+8)
        float sl = 0.f, ql = 0.f, sh = 0.f, qh = 0.f;
        #pragma unroll
        for (int nt = 0; nt < 4; nt++) {
            int c = cb + nt * 8 + tid4 * 2;
            float b0 = bks[c], b1 = bks[c + 1];
            dd[nt][0] += b0; dd[nt][1] += b1;
            dd[nt][2] += b0; dd[nt][3] += b1;
            sl += dd[nt][0] + dd[nt][1];
            ql += dd[nt][0] * dd[nt][0] + dd[nt][1] * dd[nt][1];
            sh += dd[nt][2] + dd[nt][3];
            qh += dd[nt][2] * dd[nt][2] + dd[nt][3] * dd[nt][3];
        }
        #pragma unroll
        for (int o = 1; o <= 2; o <<= 1) {
            sl += __shfl_xor_sync(0xffffffffu, sl, o);
            ql += __shfl_xor_sync(0xffffffffu, ql, o);
            sh += __shfl_xor_sync(0xffffffffu, sh, o);
            qh += __shfl_xor_sync(0xffffffffu, qh, o);
        }
        if (tid4 == 0) {
            redS[gid][w] = sl;     redQ[gid][w] = ql;
            redS[gid + 8][w] = sh; redQ[gid + 8][w] = qh;
        }
        __syncthreads();
        if (tid < 16) {
            float s = 0.f, q = 0.f;
            #pragma unroll
            for (int ww = 0; ww < 8; ww++) { s += redS[tid][ww]; q += redQ[tid][ww]; }
            float mu = s * (1.f / 256.f);
            smu[tid] = mu;
            srs[tid] = rsqrtf(q * (1.f / 256.f) - mu * mu + 1e-5f);
        }
        __syncthreads();

        bool vlo = (g0 + gid) < e1;
        bool vhi = (g0 + gid + 8) < e1;
        float mul = smu[gid], rsl = srs[gid];
        float muh = smu[gid + 8], rsh = srs[gid + 8];
        #pragma unroll
        for (int nt = 0; nt < 4; nt++) {
            int c = cb + nt * 8 + tid4 * 2;
            float gg0 = gks[c], gg1 = gks[c + 1];
            float ee0 = bes[c], ee1 = bes[c + 1];
            if (vlo) {
                kacc[nt][0] += fmaxf((dd[nt][0] - mul) * rsl * gg0 + ee0, 0.f);
                kacc[nt][1] += fmaxf((dd[nt][1] - mul) * rsl * gg1 + ee1, 0.f);
            }
            if (vhi) {
                kacc[nt][0] += fmaxf((dd[nt][2] - muh) * rsh * gg0 + ee0, 0.f);
                kacc[nt][1] += fmaxf((dd[nt][3] - muh) * rsh * gg1 + ee1, 0.f);
            }
        }
        __syncthreads();   // before As2/red reuse next group
    }

    // reduce kacc across the 8 lanes (gid 0..7) holding the same columns
    #pragma unroll
    for (int o = 4; o <= 16; o <<= 1) {
        #pragma unroll
        for (int nt = 0; nt < 4; nt++) {
            kacc[nt][0] += __shfl_xor_sync(0xffffffffu, kacc[nt][0], o);
            kacc[nt][1] += __shfl_xor_sync(0xffffffffu, kacc[nt][1], o);
        }
    }
    if (gid == 0) {
        #pragma unroll
        for (int nt = 0; nt < 4; nt++) {
            int c = cb + nt * 8 + tid4 * 2;
            kf[(size_t)d * OUTD + c] = kacc[nt][0];
            kf[(size_t)d * OUTD + c + 1] = kacc[nt][1];
        }
    }
}

// ---------------- fp16 tensor-core GEMM (fp32 accum): C[M,N] = A[M,K]*op(B) + bias ----------------
template <bool TRANSB, typename OUTT>
__global__ void __launch_bounds__(256, 2)
hgemm(const float* __restrict__ A, const float* __restrict__ B,
      const float* __restrict__ bias, OUTT* __restrict__ C,
      int M, int N, int Kd) {
    const int LDA = 136;
    __shared__ uint32_t As[8 * LDA];
    __shared__ uint32_t Bs[8 * LDA];
    int tid = threadIdx.x;
    int lane = tid & 31, w = tid >> 5;
    int gid = lane >> 2, tid4 = lane & 3;
    int wm = w & 1, wn = w >> 1;
    int bm = blockIdx.y * 128, bn = blockIdx.x * 128;

    float d[4][4][4];
    #pragma unroll
    for (int i = 0; i < 4; i++)
        #pragma unroll
        for (int j = 0; j < 4; j++)
            #pragma unroll
            for (int q = 0; q < 4; q++) d[i][j][q] = 0.f;

    for (int k0 = 0; k0 < Kd; k0 += 16) {
        {
            int row = tid >> 1, kb = (tid & 1) * 8;
            int gr = bm + row;
            float4 v0 = make_float4(0.f, 0.f, 0.f, 0.f);
            float4 v1 = v0;
            if (gr < M) {
                v0 = *(const float4*)(A + (size_t)gr * Kd + k0 + kb);
                v1 = *(const float4*)(A + (size_t)gr * Kd + k0 + kb + 4);
            }
            int kb2 = kb >> 1;
            As[(kb2 + 0) * LDA + row] = f2h2(v0.x, v0.y);
            As[(kb2 + 1) * LDA + row] = f2h2(v0.z, v0.w);
            As[(kb2 + 2) * LDA + row] = f2h2(v1.x, v1.y);
            As[(kb2 + 3) * LDA + row] = f2h2(v1.z, v1.w);
        }
        if (!TRANSB) {
            int k2 = tid >> 5, c4 = (tid & 31) * 4;
            float4 va = *(const float4*)(B + (size_t)(k0 + 2 * k2) * N + bn + c4);
            float4 vb = *(const float4*)(B + (size_t)(k0 + 2 * k2 + 1) * N + bn + c4);
            uint4 u;
            u.x = f2h2(va.x, vb.x);
            u.y = f2h2(va.y, vb.y);
            u.z = f2h2(va.z, vb.z);
            u.w = f2h2(va.w, vb.w);
            *(uint4*)(&Bs[k2 * LDA + c4]) = u;
        } else {
            #pragma unroll
            for (int h = 0; h < 2; h++) {
                int id = tid + h * 256;
                int n = id >> 2, kq = (id & 3) * 4;
                float4 v = *(const float4*)(B + (size_t)(bn + n) * Kd + k0 + kq);
                int k2 = kq >> 1;
                Bs[(k2 + 0) * LDA + n] = f2h2(v.x, v.y);
                Bs[(k2 + 1) * LDA + n] = f2h2(v.z, v.w);
            }
        }
        __syncthreads();
        {
            uint32_t af[4][4], bf[4][2];
            #pragma unroll
            for (int mt = 0; mt < 4; mt++) {
                int rb = wm * 64 + mt * 16;
                af[mt][0] = As[tid4 * LDA + rb + gid];
                af[mt][1] = As[tid4 * LDA + rb + gid + 8];
                af[mt][2] = As[(tid4 + 4) * LDA + rb + gid];
                af[mt][3] = As[(tid4 + 4) * LDA + rb + gid + 8];
            }
            #pragma unroll
            for (int nt = 0; nt < 4; nt++) {
                int cb = wn * 32 + nt * 8;
                bf[nt][0] = Bs[tid4 * LDA + cb + gid];
                bf[nt][1] = Bs[(tid4 + 4) * LDA + cb + gid];
            }
            #pragma unroll
            for (int mt = 0; mt < 4; mt++)
                #pragma unroll
                for (int nt = 0; nt < 4; nt++)
                    mma_f16(d[mt][nt], af[mt], bf[nt]);
        }
        __syncthreads();
    }
    #pragma unroll
    for (int mt = 0; mt < 4; mt++) {
        int r0 = bm + wm * 64 + mt * 16 + gid;
        int r1 = r0 + 8;
        #pragma unroll
        for (int nt = 0; nt < 4; nt++) {
            int cc = bn + wn * 32 + nt * 8 + tid4 * 2;
            float b0 = bias ? bias[cc] : 0.f;
            float b1 = bias ? bias[cc + 1] : 0.f;
            if (r0 < M) {
                float v0 = d[mt][nt][0] + b0, v1 = d[mt][nt][1] + b1;
                if (sizeof(OUTT) == 2) {
                    *(__half2*)((__half*)C + (size_t)r0 * N + cc) = __floats2half2_rn(v0, v1);
                } else {
                    *(float2*)((float*)C + (size_t)r0 * N + cc) = make_float2(v0, v1);
                }
            }
            if (r1 < M) {
                float v0 = d[mt][nt][2] + b0, v1 = d[mt][nt][3] + b1;
                if (sizeof(OUTT) == 2) {
                    *(__half2*)((__half*)C + (size_t)r1 * N + cc) = __floats2half2_rn(v0, v1);
                } else {
                    *(float2*)((float*)C + (size_t)r1 * N + cc) = make_float2(v0, v1);
                }
            }
        }
    }
}

// ---------------- GRU elementwise + relu + LN + build cat (fp16 gi/gh) ----------------
__global__ void k_gru(const __half* __restrict__ gi, const __half* __restrict__ gh,
                      const float* __restrict__ nf, const float* __restrict__ g_ln,
                      const float* __restrict__ b_ln, const float* __restrict__ kfeat,
                      float* __restrict__ cat_) {
    int v = blockIdx.x;
    int o = threadIdx.x;  // 256
    size_t b3 = (size_t)v * (3 * Dg);
    float ir = __half2float(gi[b3 + o]);
    float iz = __half2float(gi[b3 + Dg + o]);
    float inn = __half2float(gi[b3 + 2 * Dg + o]);
    float hr = __half2float(gh[b3 + o]);
    float hz = __half2float(gh[b3 + Dg + o]);
    float hn = __half2float(gh[b3 + 2 * Dg + o]);
    float x = nf[(size_t)v * Dg + o];
    float r = 1.f / (1.f + expf(-(ir + hr)));
    float z = 1.f / (1.f + expf(-(iz + hz)));
    float n = tanhf(inn + r * hn);
    float h = (1.f - z) * n + z * x;
    h = fmaxf(h, 0.f);
    float mu, rs;
    ln_stats_256(h, &mu, &rs);
    float g = (h - mu) * rs * g_ln[o] + b_ln[o];
    cat_[(size_t)v * (Dg + OUTD) + o] = g;
    cat_[(size_t)v * (Dg + OUTD) + Dg + o] = kfeat[(size_t)v * OUTD + o];
}

// ---------------- final LN + relu (in place on d_out) ----------------
__global__ void k_outln(float* __restrict__ out, const float* __restrict__ gc,
                        const float* __restrict__ betac) {
    int v = blockIdx.x;
    int o = threadIdx.x;
    float y = out[(size_t)v * Dg + o];
    float mu, rs;
    ln_stats_256(y, &mu, &rs);
    out[(size_t)v * Dg + o] = fmaxf((y - mu) * rs * gc[o] + betac[o], 0.f);
}

// ---------------- launch ----------------
extern "C" void kernel_launch(void* const* d_in, const int* in_sizes, int n_in,
                              void* d_out, int out_size) {
    const float* nf    = (const float*)d_in[0];
    const int*   src   = (const int*)d_in[1];
    const int*   dst   = (const int*)d_in[2];
    const float* Wp    = (const float*)d_in[3];
    const float* bp    = (const float*)d_in[4];
    const float* gp    = (const float*)d_in[5];
    const float* betap = (const float*)d_in[6];
    const float* Wk    = (const float*)d_in[7];
    const float* bk    = (const float*)d_in[8];
    const float* gk    = (const float*)d_in[9];
    const float* betak = (const float*)d_in[10];
    const float* We    = (const float*)d_in[11];
    const float* be    = (const float*)d_in[12];
    const float* Wn    = (const float*)d_in[13];
    const float* bn    = (const float*)d_in[14];
    const float* W_ih  = (const float*)d_in[15];
    const float* W_hh  = (const float*)d_in[16];
    const float* b_ih  = (const float*)d_in[17];
    const float* b_hh  = (const float*)d_in[18];
    const float* g_ln  = (const float*)d_in[19];
    const float* b_ln  = (const float*)d_in[20];
    const float* Wc    = (const float*)d_in[21];
    const float* bc    = (const float*)d_in[22];
    const float* gc    = (const float*)d_in[23];
    const float* betac = (const float*)d_in[24];

    int V = in_sizes[0] / Dg;
    int E = in_sizes[1];
    float* out = (float*)d_out;

    float *npj, *Wkp, *ad, *as_, *att, *ctx, *kf, *cat_;
    __half *T, *hv, *gi, *gh, *npjh;
    uint32_t* npjh2;
    int *deg, *offs, *cursor, *eids, *bsums;
    cudaGetSymbolAddress((void**)&npj, g_npj);
    cudaGetSymbolAddress((void**)&npjh2, g_npjh);
    npjh = (__half*)npjh2;
    cudaGetSymbolAddress((void**)&Wkp, g_Wkp);
    cudaGetSymbolAddress((void**)&ad, g_ad);
    cudaGetSymbolAddress((void**)&as_, g_as);
    cudaGetSymbolAddress((void**)&hv, g_hv);
    cudaGetSymbolAddress((void**)&T, g_T);
    cudaGetSymbolAddress((void**)&att, g_att);
    cudaGetSymbolAddress((void**)&ctx, g_ctx);
    cudaGetSymbolAddress((void**)&kf, g_kf);
    cudaGetSymbolAddress((void**)&gi, g_gi);
    cudaGetSymbolAddress((void**)&gh, g_gh);
    cudaGetSymbolAddress((void**)&cat_, g_cat);
    cudaGetSymbolAddress((void**)&deg, g_deg);
    cudaGetSymbolAddress((void**)&offs, g_offs);
    cudaGetSymbolAddress((void**)&cursor, g_cursor);
    cudaGetSymbolAddress((void**)&eids, g_eids);
    cudaGetSymbolAddress((void**)&bsums, g_bsums);

    cudaMemsetAsync(deg, 0, (size_t)V * sizeof(int));

    int nb_npj = (V + 7) / 8;
    int nb_wkp = (KPAD * Kp * OUTD) / 256;
    int nb_scan = (V + 255) / 256;

    // 1: fused preamble (npj+npjh || Wkp || hist)
    k_pre<<<nb_npj + nb_wkp + HIST_BLOCKS, 256>>>(nf, Wp, bp, gp, betap, We, Wk, dst,
                                                  npj, npjh, ad, as_, Wkp, deg, V, E);
    // 2-4: fast scan -> offs + cursor
    k_scan_part<<<nb_scan, 256>>>(deg, offs, bsums, V);
    k_scan_mid<<<1, 256>>>(bsums, nb_scan);
    k_scan_apply<<<nb_scan, 256>>>(offs, cursor, bsums, V, E);
    // 5: T' = npj @ W' (o-major, fp16 out)
    {
        dim3 grid(Kp * OUTD / 128, (V + 127) / 128);
        hgemm<false, __half><<<grid, 256>>>(npj, Wkp, nullptr, T, V, Kp * OUTD, KPAD);
    }
    // 6: scatter -> eids
    k_scatter<<<592, 256>>>(dst, cursor, eids, E);
    // 7: hv = nf @ Wn + bn  (fp16 out)
    {
        dim3 grid(Dg / 128, (V + 127) / 128);
        hgemm<false, __half><<<grid, 256>>>(nf, Wn, bn, hv, V, Dg, Dg);
    }
    // 8: gh = nf @ W_hh^T + b_hh  (fp16 out)
    {
        dim3 grid(3 * Dg / 128, (V + 127) / 128);
        hgemm<true, __half><<<grid, 256>>>(nf, W_hh, b_hh, gh, V, 3 * Dg, Dg);
    }
    // 9: fused edge kernel (attn || kron-mma)
    k_edge<<<nb_npj + V, 256>>>(src, eids, offs, npjh2, T, bk, gk, betak,
                                ad, as_, be, hv, att, ctx, kf, V);
    // 10: gi = ctx @ W_ih^T + b_ih  (fp16 out)
    {
        dim3 grid(3 * Dg / 128, (V + 127) / 128);
        hgemm<true, __half><<<grid, 256>>>(ctx, W_ih, b_ih, gi, V, 3 * Dg, Dg);
    }
    // 11: GRU elementwise + LN + cat build
    k_gru<<<V, 256>>>(gi, gh, nf, g_ln, b_ln, kf, cat_);
    // 12: out = cat @ Wc + bc
    {
        dim3 grid(Dg / 128, (V + 127) / 128);
        hgemm<false, float><<<grid, 256>>>(cat_, Wc, bc, out, V, Dg, Dg + OUTD);
    }
    // 13: final LN + relu
    k_outln<<<V, 256>>>(out, gc, betac);
}

// round 11
// speedup vs baseline: 1.1836x; 1.1836x over previous
#include <cuda_runtime.h>
#include <cuda_bf16.h>
#include <cuda_fp16.h>
#include <math.h>
#include <stdint.h>

// ---------------- problem constants ----------------
#define VMAX 50000
#define EMAX 600000
#define Dg   256
#define Kp   20     // kron projection dim
#define KPAD 32     // padded projection dim for tensor-core GEMM
#define OUTD 256

// ---------------- device scratch (static; no allocation allowed) ----------------
__device__ float  g_npj[(size_t)VMAX * KPAD];        // padded, cols 20..31 = 0
__device__ float  g_Wkp[(size_t)KPAD * Kp * OUTD];   // W' = transposed Wk, 32 x 5120 (a-major)
__device__ float  g_ad[VMAX];
__device__ float  g_as[VMAX];
__device__ __half g_hv[(size_t)VMAX * Dg];           // fp16
__device__ __half g_T[(size_t)VMAX * Kp * OUTD];     // 512 MB fp16, a-major [v][a*256+o]
__device__ int    g_deg[VMAX];
__device__ int    g_offs[VMAX + 1];
__device__ int    g_bsums[256];
__device__ int    g_cursor[VMAX];
__device__ int    g_eids[EMAX];
__device__ float  g_att[EMAX];
__device__ float  g_ctx[(size_t)VMAX * Dg];
__device__ float  g_kf[(size_t)VMAX * OUTD];
__device__ __half g_gi[(size_t)VMAX * 3 * Dg];       // fp16
__device__ __half g_gh[(size_t)VMAX * 3 * Dg];       // fp16
__device__ float  g_cat[(size_t)VMAX * (Dg + OUTD)];

// ---------------- helpers ----------------
__device__ __forceinline__ float warp_sum(float v) {
    #pragma unroll
    for (int o = 16; o; o >>= 1) v += __shfl_xor_sync(0xffffffffu, v, o);
    return v;
}
__device__ __forceinline__ float warp_max(float v) {
    #pragma unroll
    for (int o = 16; o; o >>= 1) v = fmaxf(v, __shfl_xor_sync(0xffffffffu, v, o));
    return v;
}
__device__ __forceinline__ uint32_t f2h2(float a, float b) {
    __half2 h = __floats2half2_rn(a, b);
    return *(uint32_t*)&h;
}
__device__ __forceinline__ void mma_f16(float* d, const uint32_t* a, const uint32_t* b) {
    asm volatile(
        "mma.sync.aligned.m16n8k16.row.col.f32.f16.f16.f32 "
        "{%0,%1,%2,%3}, {%4,%5,%6,%7}, {%8,%9}, {%0,%1,%2,%3};\n"
        : "+f"(d[0]), "+f"(d[1]), "+f"(d[2]), "+f"(d[3])
        : "r"(a[0]), "r"(a[1]), "r"(a[2]), "r"(a[3]), "r"(b[0]), "r"(b[1]));
}

// block (256 thr) LN stats over one value per thread
__device__ __forceinline__ void ln_stats_256(float v, float* mu, float* rs) {
    __shared__ float s1[8], s2[8];
    float a = v, b = v * v;
    a = warp_sum(a); b = warp_sum(b);
    int w = threadIdx.x >> 5, l = threadIdx.x & 31;
    if (l == 0) { s1[w] = a; s2[w] = b; }
    __syncthreads();
    if (w == 0) {
        a = (l < 8) ? s1[l] : 0.f;
        b = (l < 8) ? s2[l] : 0.f;
        #pragma unroll
        for (int o = 4; o; o >>= 1) { a += __shfl_xor_sync(0xffffffffu, a, o); b += __shfl_xor_sync(0xffffffffu, b, o); }
        if (l == 0) { s1[0] = a; s2[0] = b; }
    }
    __syncthreads();
    float m = s1[0] * (1.f / 256.f);
    float var = s2[0] * (1.f / 256.f) - m * m;
    *mu = m;
    *rs = rsqrtf(var + 1e-5f);
}

// ---------------- fused preamble: npj (+att partials)  ||  Wkp transpose  ||  dst histogram ----------------
#define HIST_BLOCKS 592
__global__ void __launch_bounds__(256)
k_pre(const float* __restrict__ nf, const float* __restrict__ Wp,
      const float* __restrict__ bp, const float* __restrict__ gp,
      const float* __restrict__ betap, const float* __restrict__ We,
      const float* __restrict__ Wk, const int* __restrict__ dst,
      float* npj, float* ad, float* as_, float* Wkp, int* deg,
      int V, int E) {
    int nb_npj = (V + 7) / 8;
    int nb_wkp = (KPAD * Kp * OUTD) / 256;   // 640
    int bid = blockIdx.x;
    if (bid < nb_npj) {
        int warp = bid * 8 + (threadIdx.x >> 5);
        int lane = threadIdx.x & 31;
        if (warp >= V) return;
        const float* x = nf + (size_t)warp * Dg;
        float xr[8];
        #pragma unroll
        for (int j = 0; j < 8; j++) xr[j] = x[j * 32 + lane];
        float pa = 0.f, pb = 0.f;
        #pragma unroll
        for (int j = 0; j < 8; j++) { int i = j * 32 + lane; pa += xr[j] * We[i]; pb += xr[j] * We[Dg + i]; }
        pa = warp_sum(pa); pb = warp_sum(pb);
        if (lane == 0) { ad[warp] = pa; as_[warp] = pb; }
        float val = 0.f;
        for (int k = 0; k < Kp; k++) {
            float p = 0.f;
            #pragma unroll
            for (int j = 0; j < 8; j++) { int i = j * 32 + lane; p += xr[j] * Wp[i * Kp + k]; }
            p = warp_sum(p);
            p += bp[k];
            if (lane == k) val = p;
        }
        float c = (lane < Kp) ? val : 0.f;
        float s = warp_sum(c);
        float s2 = warp_sum(c * c);
        float mu = s / (float)Kp;
        float var = s2 / (float)Kp - mu * mu;
        float rs = rsqrtf(var + 1e-5f);
        float y = (lane < Kp) ? fmaxf((val - mu) * rs * gp[lane] + betap[lane], 0.f) : 0.f;
        npj[(size_t)warp * KPAD + lane] = y;
    } else if (bid < nb_npj + nb_wkp) {
        // a-major: Wkp[k][a*256+o] = Wk[(a*20+k)*256 + o]
        int idx = (bid - nb_npj) * 256 + threadIdx.x;
        int k = idx / (Kp * OUTD);
        int n = idx % (Kp * OUTD);
        int a = n / OUTD, o = n % OUTD;
        Wkp[idx] = (k < Kp) ? Wk[(size_t)(a * Kp + k) * OUTD + o] : 0.f;
    } else {
        int vb = bid - nb_npj - nb_wkp;
        int stride = HIST_BLOCKS * 256;
        for (int i = vb * 256 + threadIdx.x; i < E; i += stride)
            atomicAdd(&deg[dst[i]], 1);
    }
}

// ---------------- fast 3-phase exclusive scan ----------------
__global__ void k_scan_part(const int* __restrict__ deg, int* offs, int* bsums, int V) {
    __shared__ int ws[8];
    int tid = threadIdx.x;
    int idx = blockIdx.x * 256 + tid;
    int v = (idx < V) ? deg[idx] : 0;
    int lane = tid & 31, w = tid >> 5;
    int x = v;
    #pragma unroll
    for (int o = 1; o < 32; o <<= 1) { int y = __shfl_up_sync(0xffffffffu, x, o); if (lane >= o) x += y; }
    if (lane == 31) ws[w] = x;
    __syncthreads();
    if (w == 0) {
        int s = (lane < 8) ? ws[lane] : 0;
        #pragma unroll
        for (int o = 1; o < 8; o <<= 1) { int y = __shfl_up_sync(0xffffffffu, s, o); if (lane >= o) s += y; }
        if (lane < 8) ws[lane] = s;
    }
    __syncthreads();
    int base = (w > 0) ? ws[w - 1] : 0;
    if (idx < V) offs[idx] = base + x - v;
    if (tid == 255) bsums[blockIdx.x] = base + x;
}
__global__ void k_scan_mid(int* bsums, int nb) {
    __shared__ int ws[8];
    int tid = threadIdx.x;
    int v = (tid < nb) ? bsums[tid] : 0;
    int lane = tid & 31, w = tid >> 5;
    int x = v;
    #pragma unroll
    for (int o = 1; o < 32; o <<= 1) { int y = __shfl_up_sync(0xffffffffu, x, o); if (lane >= o) x += y; }
    if (lane == 31) ws[w] = x;
    __syncthreads();
    if (w == 0) {
        int s = (lane < 8) ? ws[lane] : 0;
        #pragma unroll
        for (int o = 1; o < 8; o <<= 1) { int y = __shfl_up_sync(0xffffffffu, s, o); if (lane >= o) s += y; }
        if (lane < 8) ws[lane] = s;
    }
    __syncthreads();
    int base = (w > 0) ? ws[w - 1] : 0;
    if (tid < nb) bsums[tid] = base + x - v;
}
__global__ void k_scan_apply(int* offs, int* cursor, const int* __restrict__ bsums, int V, int E) {
    int idx = blockIdx.x * 256 + threadIdx.x;
    if (idx < V) {
        int o = offs[idx] + bsums[blockIdx.x];
        offs[idx] = o;
        cursor[idx] = o;
    }
    if (idx == 0) offs[V] = E;
}

__global__ void k_scatter(const int* __restrict__ dst, int* cursor, int* eids, int E) {
    for (int i = blockIdx.x * blockDim.x + threadIdx.x; i < E; i += gridDim.x * blockDim.x) {
        int p = atomicAdd(&cursor[dst[i]], 1);
        eids[p] = i;
    }
}

// ---------------- fused edge kernel: attn (gather, fp16 hv) || kron (smem GEMV) ----------------
__global__ void __launch_bounds__(256)
k_edge(const int* __restrict__ src, const int* __restrict__ eids,
       const int* __restrict__ offs, const float* __restrict__ npj,
       const __half* __restrict__ T, const float* __restrict__ bk,
       const float* __restrict__ gk, const float* __restrict__ betak,
       const float* __restrict__ ad, const float* __restrict__ as_,
       const float* __restrict__ be, const __half* __restrict__ hv,
       float* __restrict__ att, float* __restrict__ ctx,
       float* __restrict__ kf, int V) {
    __shared__ float Tsh[Kp * OUTD];
    __shared__ float bks[OUTD], gks[OUTD], bes[OUTD];
    __shared__ float kfs[OUTD];
    int nb_attn = (V + 7) / 8;
    int bid = blockIdx.x;
    int tid = threadIdx.x;
    int lane = tid & 31, w = tid >> 5;

    if (bid < nb_attn) {
        // ================= attention + context =================
        int node = bid * 8 + w;
        if (node >= V) return;
        int e0 = offs[node], e1 = offs[node + 1];
        float b = be[0];
        float advv = ad[node];
        float mx = -1e30f;
        for (int i = e0 + lane; i < e1; i += 32) {
            int e = eids[i];
            float lg = fmaxf(advv + as_[src[e]] + b, 0.f);
            att[i] = lg;
            mx = fmaxf(mx, lg);
        }
        mx = warp_max(mx);
        float sm = 0.f;
        for (int i = e0 + lane; i < e1; i += 32) {
            float ex = expf(att[i] - mx);
            att[i] = ex;
            sm += ex;
        }
        sm = warp_sum(sm);
        float inv = (sm > 0.f) ? 1.f / sm : 0.f;
        float c[8];
        #pragma unroll
        for (int j = 0; j < 8; j++) c[j] = 0.f;
        int nw = 0; float ww = 0.f;
        if (e0 < e1) { nw = src[eids[e0]]; ww = att[e0] * inv; }
        for (int i = e0; i < e1; i++) {
            int cs = nw; float cw = ww;
            if (i + 1 < e1) { nw = src[eids[i + 1]]; ww = att[i + 1] * inv; }
            const uint4* hp = (const uint4*)(hv + (size_t)cs * Dg) + lane;
            uint4 u = *hp;
            float2 f0 = __half22float2(*(__half2*)&u.x);
            float2 f1 = __half22float2(*(__half2*)&u.y);
            float2 f2 = __half22float2(*(__half2*)&u.z);
            float2 f3 = __half22float2(*(__half2*)&u.w);
            c[0] = fmaf(cw, f0.x, c[0]); c[1] = fmaf(cw, f0.y, c[1]);
            c[2] = fmaf(cw, f1.x, c[2]); c[3] = fmaf(cw, f1.y, c[3]);
            c[4] = fmaf(cw, f2.x, c[4]); c[5] = fmaf(cw, f2.y, c[5]);
            c[6] = fmaf(cw, f3.x, c[6]); c[7] = fmaf(cw, f3.y, c[7]);
        }
        float4 o0, o1;
        o0.x = fmaxf(c[0], 0.f); o0.y = fmaxf(c[1], 0.f);
        o0.z = fmaxf(c[2], 0.f); o0.w = fmaxf(c[3], 0.f);
        o1.x = fmaxf(c[4], 0.f); o1.y = fmaxf(c[5], 0.f);
        o1.z = fmaxf(c[6], 0.f); o1.w = fmaxf(c[7], 0.f);
        float4* cp = (float4*)(ctx + (size_t)node * Dg) + lane * 2;
        cp[0] = o0; cp[1] = o1;
        return;
    }

    // ================= kron branch (scalar smem GEMV) =================
    int d = bid - nb_attn;
    const __half2* Tg = (const __half2*)(T + (size_t)d * (Kp * OUTD));
    #pragma unroll
    for (int i = 0; i < Kp * OUTD / 2 / 256; i++) {
        int idx = i * 256 + tid;
        float2 f = __half22float2(Tg[idx]);
        Tsh[2 * idx] = f.x;
        Tsh[2 * idx + 1] = f.y;
    }
    bks[tid] = bk[tid];
    gks[tid] = gk[tid];
    bes[tid] = betak[tid];
    kfs[tid] = 0.f;
    __syncthreads();
    int e0 = offs[d], e1 = offs[d + 1];
    float kacc[8];
    #pragma unroll
    for (int j = 0; j < 8; j++) kacc[j] = 0.f;

    for (int base = e0 + w * 4; base < e1; base += 32) {
        int ne = e1 - base; if (ne > 4) ne = 4;
        float pv0 = 0.f, pv1 = 0.f, pv2 = 0.f, pv3 = 0.f;
        if (lane < Kp) {
            { int s = src[eids[base]]; pv0 = npj[(size_t)s * KPAD + lane]; }
            if (ne > 1) { int s = src[eids[base + 1]]; pv1 = npj[(size_t)s * KPAD + lane]; }
            if (ne > 2) { int s = src[eids[base + 2]]; pv2 = npj[(size_t)s * KPAD + lane]; }
            if (ne > 3) { int s = src[eids[base + 3]]; pv3 = npj[(size_t)s * KPAD + lane]; }
        }
        float y[4][8];
        #pragma unroll
        for (int j = 0; j < 8; j++) {
            float b = bks[j * 32 + lane];
            y[0][j] = b; y[1][j] = b; y[2][j] = b; y[3][j] = b;
        }
        #pragma unroll
        for (int a = 0; a < Kp; a++) {
            float p0 = __shfl_sync(0xffffffffu, pv0, a);
            float p1 = __shfl_sync(0xffffffffu, pv1, a);
            float p2 = __shfl_sync(0xffffffffu, pv2, a);
            float p3 = __shfl_sync(0xffffffffu, pv3, a);
            #pragma unroll
            for (int j = 0; j < 8; j++) {
                float tv = Tsh[a * OUTD + j * 32 + lane];
                y[0][j] = fmaf(p0, tv, y[0][j]);
                y[1][j] = fmaf(p1, tv, y[1][j]);
                y[2][j] = fmaf(p2, tv, y[2][j]);
                y[3][j] = fmaf(p3, tv, y[3][j]);
            }
        }
        #pragma unroll
        for (int t = 0; t < 4; t++) {
            if (t < ne) {
                float sA = 0.f, sB = 0.f;
                #pragma unroll
                for (int j = 0; j < 8; j++) { sA += y[t][j]; sB += y[t][j] * y[t][j]; }
                sA = warp_sum(sA); sB = warp_sum(sB);
                float mu = sA * (1.f / 256.f);
                float rs = rsqrtf(sB * (1.f / 256.f) - mu * mu + 1e-5f);
                #pragma unroll
                for (int j = 0; j < 8; j++) {
                    int o = j * 32 + lane;
                    kacc[j] += fmaxf((y[t][j] - mu) * rs * gks[o] + bes[o], 0.f);
                }
            }
        }
    }
    #pragma unroll
    for (int j = 0; j < 8; j++) atomicAdd(&kfs[j * 32 + lane], kacc[j]);
    __syncthreads();
    kf[(size_t)d * OUTD + tid] = kfs[tid];
}

// ---------------- fp16 tensor-core GEMM, 2-stage double-buffered ----------------
template <bool TRANSB, typename OUTT>
__global__ void __launch_bounds__(256, 2)
hgemm(const float* __restrict__ A, const float* __restrict__ B,
      const float* __restrict__ bias, OUTT* __restrict__ C,
      int M, int N, int Kd) {
    const int LDA = 136;
    __shared__ uint32_t As[2][8 * LDA];
    __shared__ uint32_t Bs[2][8 * LDA];
    int tid = threadIdx.x;
    int lane = tid & 31, w = tid >> 5;
    int gid = lane >> 2, tid4 = lane & 3;
    int wm = w & 1, wn = w >> 1;
    int bm = blockIdx.y * 128, bn = blockIdx.x * 128;

    float d[4][4][4];
    #pragma unroll
    for (int i = 0; i < 4; i++)
        #pragma unroll
        for (int j = 0; j < 4; j++)
            #pragma unroll
            for (int q = 0; q < 4; q++) d[i][j][q] = 0.f;

    int arow = tid >> 1, akb = (tid & 1) * 8;
    int nIter = Kd / 16;

    float4 av0, av1, bv0, bv1;
    // ---- prologue: load tile 0 ----
    {
        int gr = bm + arow;
        av0 = make_float4(0.f, 0.f, 0.f, 0.f); av1 = av0;
        if (gr < M) {
            av0 = *(const float4*)(A + (size_t)gr * Kd + akb);
            av1 = *(const float4*)(A + (size_t)gr * Kd + akb + 4);
        }
        if (!TRANSB) {
            int k2 = tid >> 5, c4 = (tid & 31) * 4;
            bv0 = *(const float4*)(B + (size_t)(2 * k2) * N + bn + c4);
            bv1 = *(const float4*)(B + (size_t)(2 * k2 + 1) * N + bn + c4);
        } else {
            int n0 = tid >> 2, kq0 = (tid & 3) * 4;
            int n1 = (tid + 256) >> 2, kq1 = ((tid + 256) & 3) * 4;
            bv0 = *(const float4*)(B + (size_t)(bn + n0) * Kd + kq0);
            bv1 = *(const float4*)(B + (size_t)(bn + n1) * Kd + kq1);
        }
    }
    // store tile 0 -> buf 0
    {
        int kb2 = akb >> 1;
        As[0][(kb2 + 0) * LDA + arow] = f2h2(av0.x, av0.y);
        As[0][(kb2 + 1) * LDA + arow] = f2h2(av0.z, av0.w);
        As[0][(kb2 + 2) * LDA + arow] = f2h2(av1.x, av1.y);
        As[0][(kb2 + 3) * LDA + arow] = f2h2(av1.z, av1.w);
        if (!TRANSB) {
            int k2 = tid >> 5, c4 = (tid & 31) * 4;
            uint4 u;
            u.x = f2h2(bv0.x, bv1.x); u.y = f2h2(bv0.y, bv1.y);
            u.z = f2h2(bv0.z, bv1.z); u.w = f2h2(bv0.w, bv1.w);
            *(uint4*)(&Bs[0][k2 * LDA + c4]) = u;
        } else {
            int n0 = tid >> 2, kq0 = (tid & 3) * 4;
            int n1 = (tid + 256) >> 2, kq1 = ((tid + 256) & 3) * 4;
            Bs[0][(kq0 / 2 + 0) * LDA + n0] = f2h2(bv0.x, bv0.y);
            Bs[0][(kq0 / 2 + 1) * LDA + n0] = f2h2(bv0.z, bv0.w);
            Bs[0][(kq1 / 2 + 0) * LDA + n1] = f2h2(bv1.x, bv1.y);
            Bs[0][(kq1 / 2 + 1) * LDA + n1] = f2h2(bv1.z, bv1.w);
        }
    }
    __syncthreads();

    for (int it = 0; it < nIter; it++) {
        int cur = it & 1;
        bool more = (it + 1 < nIter);
        // ---- prefetch next tile into registers ----
        if (more) {
            int k0 = (it + 1) * 16;
            int gr = bm + arow;
            av0 = make_float4(0.f, 0.f, 0.f, 0.f); av1 = av0;
            if (gr < M) {
                av0 = *(const float4*)(A + (size_t)gr * Kd + k0 + akb);
                av1 = *(const float4*)(A + (size_t)gr * Kd + k0 + akb + 4);
            }
            if (!TRANSB) {
                int k2 = tid >> 5, c4 = (tid & 31) * 4;
                bv0 = *(const float4*)(B + (size_t)(k0 + 2 * k2) * N + bn + c4);
                bv1 = *(const float4*)(B + (size_t)(k0 + 2 * k2 + 1) * N + bn + c4);
            } else {
                int n0 = tid >> 2, kq0 = (tid & 3) * 4;
                int n1 = (tid + 256) >> 2, kq1 = ((tid + 256) & 3) * 4;
                bv0 = *(const float4*)(B + (size_t)(bn + n0) * Kd + k0 + kq0);
                bv1 = *(const float4*)(B + (size_t)(bn + n1) * Kd + k0 + kq1);
            }
        }
        // ---- mma on current buffer ----
        {
            uint32_t af[4][4], bf[4][2];
            #pragma unroll
            for (int mt = 0; mt < 4; mt++) {
                int rb = wm * 64 + mt * 16;
                af[mt][0] = As[cur][tid4 * LDA + rb + gid];
                af[mt][1] = As[cur][tid4 * LDA + rb + gid + 8];
                af[mt][2] = As[cur][(tid4 + 4) * LDA + rb + gid];
                af[mt][3] = As[cur][(tid4 + 4) * LDA + rb + gid + 8];
            }
            #pragma unroll
            for (int nt = 0; nt < 4; nt++) {
                int cb = wn * 32 + nt * 8;
                bf[nt][0] = Bs[cur][tid4 * LDA + cb + gid];
                bf[nt][1] = Bs[cur][(tid4 + 4) * LDA + cb + gid];
            }
            #pragma unroll
            for (int mt = 0; mt < 4; mt++)
                #pragma unroll
                for (int nt = 0; nt < 4; nt++)
                    mma_f16(d[mt][nt], af[mt], bf[nt]);
        }
        // ---- store next tile -> alternate buffer ----
        if (more) {
            int nxt = cur ^ 1;
            int kb2 = akb >> 1;
            As[nxt][(kb2 + 0) * LDA + arow] = f2h2(av0.x, av0.y);
            As[nxt][(kb2 + 1) * LDA + arow] = f2h2(av0.z, av0.w);
            As[nxt][(kb2 + 2) * LDA + arow] = f2h2(av1.x, av1.y);
            As[nxt][(kb2 + 3) * LDA + arow] = f2h2(av1.z, av1.w);
            if (!TRANSB) {
                int k2 = tid >> 5, c4 = (tid & 31) * 4;
                uint4 u;
                u.x = f2h2(bv0.x, bv1.x); u.y = f2h2(bv0.y, bv1.y);
                u.z = f2h2(bv0.z, bv1.z); u.w = f2h2(bv0.w, bv1.w);
                *(uint4*)(&Bs[nxt][k2 * LDA + c4]) = u;
            } else {
                int n0 = tid >> 2, kq0 = (tid & 3) * 4;
                int n1 = (tid + 256) >> 2, kq1 = ((tid + 256) & 3) * 4;
                Bs[nxt][(kq0 / 2 + 0) * LDA + n0] = f2h2(bv0.x, bv0.y);
                Bs[nxt][(kq0 / 2 + 1) * LDA + n0] = f2h2(bv0.z, bv0.w);
                Bs[nxt][(kq1 / 2 + 0) * LDA + n1] = f2h2(bv1.x, bv1.y);
                Bs[nxt][(kq1 / 2 + 1) * LDA + n1] = f2h2(bv1.z, bv1.w);
            }
            __syncthreads();
        }
    }
    // ---- epilogue ----
    #pragma unroll
    for (int mt = 0; mt < 4; mt++) {
        int r0 = bm + wm * 64 + mt * 16 + gid;
        int r1 = r0 + 8;
        #pragma unroll
        for (int nt = 0; nt < 4; nt++) {
            int cc = bn + wn * 32 + nt * 8 + tid4 * 2;
            float b0 = bias ? bias[cc] : 0.f;
            float b1 = bias ? bias[cc + 1] : 0.f;
            if (r0 < M) {
                float v0 = d[mt][nt][0] + b0, v1 = d[mt][nt][1] + b1;
                if (sizeof(OUTT) == 2) {
                    *(__half2*)((__half*)C + (size_t)r0 * N + cc) = __floats2half2_rn(v0, v1);
                } else {
                    *(float2*)((float*)C + (size_t)r0 * N + cc) = make_float2(v0, v1);
                }
            }
            if (r1 < M) {
                float v0 = d[mt][nt][2] + b0, v1 = d[mt][nt][3] + b1;
                if (sizeof(OUTT) == 2) {
                    *(__half2*)((__half*)C + (size_t)r1 * N + cc) = __floats2half2_rn(v0, v1);
                } else {
                    *(float2*)((float*)C + (size_t)r1 * N + cc) = make_float2(v0, v1);
                }
            }
        }
    }
}

// ---------------- GRU elementwise + relu + LN + build cat (fp16 gi/gh) ----------------
__global__ void k_gru(const __half* __restrict__ gi, const __half* __restrict__ gh,
                      const float* __restrict__ nf, const float* __restrict__ g_ln,
                      const float* __restrict__ b_ln, const float* __restrict__ kfeat,
                      float* __restrict__ cat_) {
    int v = blockIdx.x;
    int o = threadIdx.x;  // 256
    size_t b3 = (size_t)v * (3 * Dg);
    float ir = __half2float(gi[b3 + o]);
    float iz = __half2float(gi[b3 + Dg + o]);
    float inn = __half2float(gi[b3 + 2 * Dg + o]);
    float hr = __half2float(gh[b3 + o]);
    float hz = __half2float(gh[b3 + Dg + o]);
    float hn = __half2float(gh[b3 + 2 * Dg + o]);
    float x = nf[(size_t)v * Dg + o];
    float r = 1.f / (1.f + expf(-(ir + hr)));
    float z = 1.f / (1.f + expf(-(iz + hz)));
    float n = tanhf(inn + r * hn);
    float h = (1.f - z) * n + z * x;
    h = fmaxf(h, 0.f);
    float mu, rs;
    ln_stats_256(h, &mu, &rs);
    float g = (h - mu) * rs * g_ln[o] + b_ln[o];
    cat_[(size_t)v * (Dg + OUTD) + o] = g;
    cat_[(size_t)v * (Dg + OUTD) + Dg + o] = kfeat[(size_t)v * OUTD + o];
}

// ---------------- final LN + relu (in place on d_out) ----------------
__global__ void k_outln(float* __restrict__ out, const float* __restrict__ gc,
                        const float* __restrict__ betac) {
    int v = blockIdx.x;
    int o = threadIdx.x;
    float y = out[(size_t)v * Dg + o];
    float mu, rs;
    ln_stats_256(y, &mu, &rs);
    out[(size_t)v * Dg + o] = fmaxf((y - mu) * rs * gc[o] + betac[o], 0.f);
}

// ---------------- launch ----------------
extern "C" void kernel_launch(void* const* d_in, const int* in_sizes, int n_in,
                              void* d_out, int out_size) {
    const float* nf    = (const float*)d_in[0];
    const int*   src   = (const int*)d_in[1];
    const int*   dst   = (const int*)d_in[2];
    const float* Wp    = (const float*)d_in[3];
    const float* bp    = (const float*)d_in[4];
    const float* gp    = (const float*)d_in[5];
    const float* betap = (const float*)d_in[6];
    const float* Wk    = (const float*)d_in[7];
    const float* bk    = (const float*)d_in[8];
    const float* gk    = (const float*)d_in[9];
    const float* betak = (const float*)d_in[10];
    const float* We    = (const float*)d_in[11];
    const float* be    = (const float*)d_in[12];
    const float* Wn    = (const float*)d_in[13];
    const float* bn    = (const float*)d_in[14];
    const float* W_ih  = (const float*)d_in[15];
    const float* W_hh  = (const float*)d_in[16];
    const float* b_ih  = (const float*)d_in[17];
    const float* b_hh  = (const float*)d_in[18];
    const float* g_ln  = (const float*)d_in[19];
    const float* b_ln  = (const float*)d_in[20];
    const float* Wc    = (const float*)d_in[21];
    const float* bc    = (const float*)d_in[22];
    const float* gc    = (const float*)d_in[23];
    const float* betac = (const float*)d_in[24];

    int V = in_sizes[0] / Dg;
    int E = in_sizes[1];
    float* out = (float*)d_out;

    float *npj, *Wkp, *ad, *as_, *att, *ctx, *kf, *cat_;
    __half *T, *hv, *gi, *gh;
    int *deg, *offs, *cursor, *eids, *bsums;
    cudaGetSymbolAddress((void**)&npj, g_npj);
    cudaGetSymbolAddress((void**)&Wkp, g_Wkp);
    cudaGetSymbolAddress((void**)&ad, g_ad);
    cudaGetSymbolAddress((void**)&as_, g_as);
    cudaGetSymbolAddress((void**)&hv, g_hv);
    cudaGetSymbolAddress((void**)&T, g_T);
    cudaGetSymbolAddress((void**)&att, g_att);
    cudaGetSymbolAddress((void**)&ctx, g_ctx);
    cudaGetSymbolAddress((void**)&kf, g_kf);
    cudaGetSymbolAddress((void**)&gi, g_gi);
    cudaGetSymbolAddress((void**)&gh, g_gh);
    cudaGetSymbolAddress((void**)&cat_, g_cat);
    cudaGetSymbolAddress((void**)&deg, g_deg);
    cudaGetSymbolAddress((void**)&offs, g_offs);
    cudaGetSymbolAddress((void**)&cursor, g_cursor);
    cudaGetSymbolAddress((void**)&eids, g_eids);
    cudaGetSymbolAddress((void**)&bsums, g_bsums);

    cudaMemsetAsync(deg, 0, (size_t)V * sizeof(int));

    int nb_npj = (V + 7) / 8;
    int nb_wkp = (KPAD * Kp * OUTD) / 256;
    int nb_scan = (V + 255) / 256;

    // 1: fused preamble (npj || Wkp || hist)
    k_pre<<<nb_npj + nb_wkp + HIST_BLOCKS, 256>>>(nf, Wp, bp, gp, betap, We, Wk, dst,
                                                  npj, ad, as_, Wkp, deg, V, E);
    // 2-4: fast scan -> offs + cursor
    k_scan_part<<<nb_scan, 256>>>(deg, offs, bsums, V);
    k_scan_mid<<<1, 256>>>(bsums, nb_scan);
    k_scan_apply<<<nb_scan, 256>>>(offs, cursor, bsums, V, E);
    // 5: T = npj @ W'  (fp16 tensor cores, fp16 out)
    {
        dim3 grid(Kp * OUTD / 128, (V + 127) / 128);
        hgemm<false, __half><<<grid, 256>>>(npj, Wkp, nullptr, T, V, Kp * OUTD, KPAD);
    }
    // 6: scatter -> eids
    k_scatter<<<592, 256>>>(dst, cursor, eids, E);
    // 7: hv = nf @ Wn + bn  (fp16 out)
    {
        dim3 grid(Dg / 128, (V + 127) / 128);
        hgemm<false, __half><<<grid, 256>>>(nf, Wn, bn, hv, V, Dg, Dg);
    }
    // 8: gh = nf @ W_hh^T + b_hh  (fp16 out)
    {
        dim3 grid(3 * Dg / 128, (V + 127) / 128);
        hgemm<true, __half><<<grid, 256>>>(nf, W_hh, b_hh, gh, V, 3 * Dg, Dg);
    }
    // 9: fused edge kernel (attn || kron)
    k_edge<<<nb_npj + V, 256>>>(src, eids, offs, npj, T, bk, gk, betak,
                                ad, as_, be, hv, att, ctx, kf, V);
    // 10: gi = ctx @ W_ih^T + b_ih  (fp16 out)
    {
        dim3 grid(3 * Dg / 128, (V + 127) / 128);
        hgemm<true, __half><<<grid, 256>>>(ctx, W_ih, b_ih, gi, V, 3 * Dg, Dg);
    }
    // 11: GRU elementwise + LN + cat build
    k_gru<<<V, 256>>>(gi, gh, nf, g_ln, b_ln, kf, cat_);
    // 12: out = cat @ Wc + bc
    {
        dim3 grid(Dg / 128, (V + 127) / 128);
        hgemm<false, float><<<grid, 256>>>(cat_, Wc, bc, out, V, Dg, Dg + OUTD);
    }
    // 13: final LN + relu
    k_outln<<<V, 256>>>(out, gc, betac);
}

// round 12
// speedup vs baseline: 1.2536x; 1.0591x over previous
#include <cuda_runtime.h>
#include <cuda_bf16.h>
#include <cuda_fp16.h>
#include <math.h>
#include <stdint.h>

// ---------------- problem constants ----------------
#define VMAX 50000
#define EMAX 600000
#define Dg   256
#define Kp   20     // kron projection dim
#define KPAD 32     // padded projection dim for tensor-core GEMM
#define OUTD 256

// ---------------- device scratch (static; no allocation allowed) ----------------
__device__ float  g_npj[(size_t)VMAX * KPAD];        // padded fp32 (kron shfl source)
__device__ __half g_npjh[(size_t)VMAX * KPAD];       // fp16 copy (T-GEMM A)
__device__ __half g_nfh[(size_t)VMAX * Dg];          // fp16 copy of node_feats (GEMM A)
__device__ float  g_Wkp[(size_t)KPAD * Kp * OUTD];   // W' = transposed Wk (a-major)
__device__ float  g_ad[VMAX];
__device__ float  g_as[VMAX];
__device__ __half g_hv[(size_t)VMAX * Dg];           // fp16
__device__ __half g_T[(size_t)VMAX * Kp * OUTD];     // 512 MB fp16, a-major [v][a*256+o]
__device__ int    g_deg[VMAX];
__device__ int    g_offs[VMAX + 1];
__device__ int    g_bsums[256];
__device__ int    g_cursor[VMAX];
__device__ int    g_eids[EMAX];
__device__ float  g_att[EMAX];
__device__ __half g_ctxh[(size_t)VMAX * Dg];         // fp16 (gi GEMM A)
__device__ float  g_kf[(size_t)VMAX * OUTD];
__device__ __half g_gi[(size_t)VMAX * 3 * Dg];       // fp16
__device__ __half g_gh[(size_t)VMAX * 3 * Dg];       // fp16
__device__ __half g_cath[(size_t)VMAX * (Dg + OUTD)];// fp16 (final GEMM A)

// ---------------- helpers ----------------
__device__ __forceinline__ float warp_sum(float v) {
    #pragma unroll
    for (int o = 16; o; o >>= 1) v += __shfl_xor_sync(0xffffffffu, v, o);
    return v;
}
__device__ __forceinline__ float warp_max(float v) {
    #pragma unroll
    for (int o = 16; o; o >>= 1) v = fmaxf(v, __shfl_xor_sync(0xffffffffu, v, o));
    return v;
}
__device__ __forceinline__ uint32_t f2h2(float a, float b) {
    __half2 h = __floats2half2_rn(a, b);
    return *(uint32_t*)&h;
}
__device__ __forceinline__ void mma_f16(float* d, const uint32_t* a, const uint32_t* b) {
    asm volatile(
        "mma.sync.aligned.m16n8k16.row.col.f32.f16.f16.f32 "
        "{%0,%1,%2,%3}, {%4,%5,%6,%7}, {%8,%9}, {%0,%1,%2,%3};\n"
        : "+f"(d[0]), "+f"(d[1]), "+f"(d[2]), "+f"(d[3])
        : "r"(a[0]), "r"(a[1]), "r"(a[2]), "r"(a[3]), "r"(b[0]), "r"(b[1]));
}

// block (256 thr) LN stats over one value per thread
__device__ __forceinline__ void ln_stats_256(float v, float* mu, float* rs) {
    __shared__ float s1[8], s2[8];
    float a = v, b = v * v;
    a = warp_sum(a); b = warp_sum(b);
    int w = threadIdx.x >> 5, l = threadIdx.x & 31;
    if (l == 0) { s1[w] = a; s2[w] = b; }
    __syncthreads();
    if (w == 0) {
        a = (l < 8) ? s1[l] : 0.f;
        b = (l < 8) ? s2[l] : 0.f;
        #pragma unroll
        for (int o = 4; o; o >>= 1) { a += __shfl_xor_sync(0xffffffffu, a, o); b += __shfl_xor_sync(0xffffffffu, b, o); }
        if (l == 0) { s1[0] = a; s2[0] = b; }
    }
    __syncthreads();
    float m = s1[0] * (1.f / 256.f);
    float var = s2[0] * (1.f / 256.f) - m * m;
    *mu = m;
    *rs = rsqrtf(var + 1e-5f);
}

// ---------------- fused preamble: npj || Wkp || hist || nf->fp16 ----------------
#define HIST_BLOCKS 592
#define NFC_BLOCKS  800
__global__ void __launch_bounds__(256)
k_pre(const float* __restrict__ nf, const float* __restrict__ Wp,
      const float* __restrict__ bp, const float* __restrict__ gp,
      const float* __restrict__ betap, const float* __restrict__ We,
      const float* __restrict__ Wk, const int* __restrict__ dst,
      float* npj, __half* npjh, __half* nfh, float* ad, float* as_,
      float* Wkp, int* deg, int V, int E) {
    int nb_npj = (V + 7) / 8;
    int nb_wkp = (KPAD * Kp * OUTD) / 256;   // 640
    int bid = blockIdx.x;
    if (bid < nb_npj) {
        int warp = bid * 8 + (threadIdx.x >> 5);
        int lane = threadIdx.x & 31;
        if (warp >= V) return;
        const float* x = nf + (size_t)warp * Dg;
        float xr[8];
        #pragma unroll
        for (int j = 0; j < 8; j++) xr[j] = x[j * 32 + lane];
        float pa = 0.f, pb = 0.f;
        #pragma unroll
        for (int j = 0; j < 8; j++) { int i = j * 32 + lane; pa += xr[j] * We[i]; pb += xr[j] * We[Dg + i]; }
        pa = warp_sum(pa); pb = warp_sum(pb);
        if (lane == 0) { ad[warp] = pa; as_[warp] = pb; }
        float val = 0.f;
        for (int k = 0; k < Kp; k++) {
            float p = 0.f;
            #pragma unroll
            for (int j = 0; j < 8; j++) { int i = j * 32 + lane; p += xr[j] * Wp[i * Kp + k]; }
            p = warp_sum(p);
            p += bp[k];
            if (lane == k) val = p;
        }
        float c = (lane < Kp) ? val : 0.f;
        float s = warp_sum(c);
        float s2 = warp_sum(c * c);
        float mu = s / (float)Kp;
        float var = s2 / (float)Kp - mu * mu;
        float rs = rsqrtf(var + 1e-5f);
        float y = (lane < Kp) ? fmaxf((val - mu) * rs * gp[lane] + betap[lane], 0.f) : 0.f;
        npj[(size_t)warp * KPAD + lane] = y;
        npjh[(size_t)warp * KPAD + lane] = __float2half(y);
    } else if (bid < nb_npj + nb_wkp) {
        // a-major: Wkp[k][a*256+o] = Wk[(a*20+k)*256 + o]
        int idx = (bid - nb_npj) * 256 + threadIdx.x;
        int k = idx / (Kp * OUTD);
        int n = idx % (Kp * OUTD);
        int a = n / OUTD, o = n % OUTD;
        Wkp[idx] = (k < Kp) ? Wk[(size_t)(a * Kp + k) * OUTD + o] : 0.f;
    } else if (bid < nb_npj + nb_wkp + HIST_BLOCKS) {
        int vb = bid - nb_npj - nb_wkp;
        int stride = HIST_BLOCKS * 256;
        for (int i = vb * 256 + threadIdx.x; i < E; i += stride)
            atomicAdd(&deg[dst[i]], 1);
    } else {
        // nf -> fp16 (pairs)
        int cb = bid - nb_npj - nb_wkp - HIST_BLOCKS;
        size_t total = (size_t)V * Dg / 2;
        const float2* src2 = (const float2*)nf;
        __half2* dst2 = (__half2*)nfh;
        for (size_t i = (size_t)cb * 256 + threadIdx.x; i < total; i += (size_t)NFC_BLOCKS * 256)
            dst2[i] = __floats2half2_rn(src2[i].x, src2[i].y);
    }
}

// ---------------- fast 3-phase exclusive scan ----------------
__global__ void k_scan_part(const int* __restrict__ deg, int* offs, int* bsums, int V) {
    __shared__ int ws[8];
    int tid = threadIdx.x;
    int idx = blockIdx.x * 256 + tid;
    int v = (idx < V) ? deg[idx] : 0;
    int lane = tid & 31, w = tid >> 5;
    int x = v;
    #pragma unroll
    for (int o = 1; o < 32; o <<= 1) { int y = __shfl_up_sync(0xffffffffu, x, o); if (lane >= o) x += y; }
    if (lane == 31) ws[w] = x;
    __syncthreads();
    if (w == 0) {
        int s = (lane < 8) ? ws[lane] : 0;
        #pragma unroll
        for (int o = 1; o < 8; o <<= 1) { int y = __shfl_up_sync(0xffffffffu, s, o); if (lane >= o) s += y; }
        if (lane < 8) ws[lane] = s;
    }
    __syncthreads();
    int base = (w > 0) ? ws[w - 1] : 0;
    if (idx < V) offs[idx] = base + x - v;
    if (tid == 255) bsums[blockIdx.x] = base + x;
}
__global__ void k_scan_mid(int* bsums, int nb) {
    __shared__ int ws[8];
    int tid = threadIdx.x;
    int v = (tid < nb) ? bsums[tid] : 0;
    int lane = tid & 31, w = tid >> 5;
    int x = v;
    #pragma unroll
    for (int o = 1; o < 32; o <<= 1) { int y = __shfl_up_sync(0xffffffffu, x, o); if (lane >= o) x += y; }
    if (lane == 31) ws[w] = x;
    __syncthreads();
    if (w == 0) {
        int s = (lane < 8) ? ws[lane] : 0;
        #pragma unroll
        for (int o = 1; o < 8; o <<= 1) { int y = __shfl_up_sync(0xffffffffu, s, o); if (lane >= o) s += y; }
        if (lane < 8) ws[lane] = s;
    }
    __syncthreads();
    int base = (w > 0) ? ws[w - 1] : 0;
    if (tid < nb) bsums[tid] = base + x - v;
}
__global__ void k_scan_apply(int* offs, int* cursor, const int* __restrict__ bsums, int V, int E) {
    int idx = blockIdx.x * 256 + threadIdx.x;
    if (idx < V) {
        int o = offs[idx] + bsums[blockIdx.x];
        offs[idx] = o;
        cursor[idx] = o;
    }
    if (idx == 0) offs[V] = E;
}

__global__ void k_scatter(const int* __restrict__ dst, int* cursor, int* eids, int E) {
    for (int i = blockIdx.x * blockDim.x + threadIdx.x; i < E; i += gridDim.x * blockDim.x) {
        int p = atomicAdd(&cursor[dst[i]], 1);
        eids[p] = i;
    }
}

// ---------------- fused edge kernel: attn (gather, fp16 hv, fp16 ctx out) || kron ----------------
__global__ void __launch_bounds__(256)
k_edge(const int* __restrict__ src, const int* __restrict__ eids,
       const int* __restrict__ offs, const float* __restrict__ npj,
       const __half* __restrict__ T, const float* __restrict__ bk,
       const float* __restrict__ gk, const float* __restrict__ betak,
       const float* __restrict__ ad, const float* __restrict__ as_,
       const float* __restrict__ be, const __half* __restrict__ hv,
       float* __restrict__ att, __half* __restrict__ ctxh,
       float* __restrict__ kf, int V) {
    __shared__ float Tsh[Kp * OUTD];
    __shared__ float bks[OUTD], gks[OUTD], bes[OUTD];
    __shared__ float kfs[OUTD];
    int nb_attn = (V + 7) / 8;
    int bid = blockIdx.x;
    int tid = threadIdx.x;
    int lane = tid & 31, w = tid >> 5;

    if (bid < nb_attn) {
        // ================= attention + context =================
        int node = bid * 8 + w;
        if (node >= V) return;
        int e0 = offs[node], e1 = offs[node + 1];
        float b = be[0];
        float advv = ad[node];
        float mx = -1e30f;
        for (int i = e0 + lane; i < e1; i += 32) {
            int e = eids[i];
            float lg = fmaxf(advv + as_[src[e]] + b, 0.f);
            att[i] = lg;
            mx = fmaxf(mx, lg);
        }
        mx = warp_max(mx);
        float sm = 0.f;
        for (int i = e0 + lane; i < e1; i += 32) {
            float ex = expf(att[i] - mx);
            att[i] = ex;
            sm += ex;
        }
        sm = warp_sum(sm);
        float inv = (sm > 0.f) ? 1.f / sm : 0.f;
        float c[8];
        #pragma unroll
        for (int j = 0; j < 8; j++) c[j] = 0.f;
        int nw = 0; float ww = 0.f;
        if (e0 < e1) { nw = src[eids[e0]]; ww = att[e0] * inv; }
        for (int i = e0; i < e1; i++) {
            int cs = nw; float cw = ww;
            if (i + 1 < e1) { nw = src[eids[i + 1]]; ww = att[i + 1] * inv; }
            const uint4* hp = (const uint4*)(hv + (size_t)cs * Dg) + lane;
            uint4 u = *hp;
            float2 f0 = __half22float2(*(__half2*)&u.x);
            float2 f1 = __half22float2(*(__half2*)&u.y);
            float2 f2 = __half22float2(*(__half2*)&u.z);
            float2 f3 = __half22float2(*(__half2*)&u.w);
            c[0] = fmaf(cw, f0.x, c[0]); c[1] = fmaf(cw, f0.y, c[1]);
            c[2] = fmaf(cw, f1.x, c[2]); c[3] = fmaf(cw, f1.y, c[3]);
            c[4] = fmaf(cw, f2.x, c[4]); c[5] = fmaf(cw, f2.y, c[5]);
            c[6] = fmaf(cw, f3.x, c[6]); c[7] = fmaf(cw, f3.y, c[7]);
        }
        // relu + fp16 pack (identical to what the gi GEMM would round to)
        uint4 o;
        o.x = f2h2(fmaxf(c[0], 0.f), fmaxf(c[1], 0.f));
        o.y = f2h2(fmaxf(c[2], 0.f), fmaxf(c[3], 0.f));
        o.z = f2h2(fmaxf(c[4], 0.f), fmaxf(c[5], 0.f));
        o.w = f2h2(fmaxf(c[6], 0.f), fmaxf(c[7], 0.f));
        *((uint4*)(ctxh + (size_t)node * Dg) + lane) = o;
        return;
    }

    // ================= kron branch (scalar smem GEMV) =================
    int d = bid - nb_attn;
    const __half2* Tg = (const __half2*)(T + (size_t)d * (Kp * OUTD));
    #pragma unroll
    for (int i = 0; i < Kp * OUTD / 2 / 256; i++) {
        int idx = i * 256 + tid;
        float2 f = __half22float2(Tg[idx]);
        Tsh[2 * idx] = f.x;
        Tsh[2 * idx + 1] = f.y;
    }
    bks[tid] = bk[tid];
    gks[tid] = gk[tid];
    bes[tid] = betak[tid];
    kfs[tid] = 0.f;
    __syncthreads();
    int e0 = offs[d], e1 = offs[d + 1];
    float kacc[8];
    #pragma unroll
    for (int j = 0; j < 8; j++) kacc[j] = 0.f;

    for (int base = e0 + w * 4; base < e1; base += 32) {
        int ne = e1 - base; if (ne > 4) ne = 4;
        float pv0 = 0.f, pv1 = 0.f, pv2 = 0.f, pv3 = 0.f;
        if (lane < Kp) {
            { int s = src[eids[base]]; pv0 = npj[(size_t)s * KPAD + lane]; }
            if (ne > 1) { int s = src[eids[base + 1]]; pv1 = npj[(size_t)s * KPAD + lane]; }
            if (ne > 2) { int s = src[eids[base + 2]]; pv2 = npj[(size_t)s * KPAD + lane]; }
            if (ne > 3) { int s = src[eids[base + 3]]; pv3 = npj[(size_t)s * KPAD + lane]; }
        }
        float y[4][8];
        #pragma unroll
        for (int j = 0; j < 8; j++) {
            float b = bks[j * 32 + lane];
            y[0][j] = b; y[1][j] = b; y[2][j] = b; y[3][j] = b;
        }
        #pragma unroll
        for (int a = 0; a < Kp; a++) {
            float p0 = __shfl_sync(0xffffffffu, pv0, a);
            float p1 = __shfl_sync(0xffffffffu, pv1, a);
            float p2 = __shfl_sync(0xffffffffu, pv2, a);
            float p3 = __shfl_sync(0xffffffffu, pv3, a);
            #pragma unroll
            for (int j = 0; j < 8; j++) {
                float tv = Tsh[a * OUTD + j * 32 + lane];
                y[0][j] = fmaf(p0, tv, y[0][j]);
                y[1][j] = fmaf(p1, tv, y[1][j]);
                y[2][j] = fmaf(p2, tv, y[2][j]);
                y[3][j] = fmaf(p3, tv, y[3][j]);
            }
        }
        #pragma unroll
        for (int t = 0; t < 4; t++) {
            if (t < ne) {
                float sA = 0.f, sB = 0.f;
                #pragma unroll
                for (int j = 0; j < 8; j++) { sA += y[t][j]; sB += y[t][j] * y[t][j]; }
                sA = warp_sum(sA); sB = warp_sum(sB);
                float mu = sA * (1.f / 256.f);
                float rs = rsqrtf(sB * (1.f / 256.f) - mu * mu + 1e-5f);
                #pragma unroll
                for (int j = 0; j < 8; j++) {
                    int o = j * 32 + lane;
                    kacc[j] += fmaxf((y[t][j] - mu) * rs * gks[o] + bes[o], 0.f);
                }
            }
        }
    }
    #pragma unroll
    for (int j = 0; j < 8; j++) atomicAdd(&kfs[j * 32 + lane], kacc[j]);
    __syncthreads();
    kf[(size_t)d * OUTD + tid] = kfs[tid];
}

// ---------------- fp16-A tensor-core GEMM, 2-stage double-buffered ----------------
// A is fp16 [M, Kd] row-major. B is fp32 weights (converted on staging).
template <bool TRANSB, typename OUTT>
__global__ void __launch_bounds__(256, 2)
hgemm(const __half* __restrict__ A, const float* __restrict__ B,
      const float* __restrict__ bias, OUTT* __restrict__ C,
      int M, int N, int Kd) {
    const int LDA = 136;
    __shared__ uint32_t As[2][8 * LDA];
    __shared__ uint32_t Bs[2][8 * LDA];
    int tid = threadIdx.x;
    int lane = tid & 31, w = tid >> 5;
    int gid = lane >> 2, tid4 = lane & 3;
    int wm = w & 1, wn = w >> 1;
    int bm = blockIdx.y * 128, bn = blockIdx.x * 128;

    float d[4][4][4];
    #pragma unroll
    for (int i = 0; i < 4; i++)
        #pragma unroll
        for (int j = 0; j < 4; j++)
            #pragma unroll
            for (int q = 0; q < 4; q++) d[i][j][q] = 0.f;

    int arow = tid >> 1, akb = (tid & 1) * 8;   // 8 halfs = 16B
    int nIter = Kd / 16;

    uint4 au;
    float4 bv0, bv1;
    // ---- prologue: load tile 0 ----
    {
        int gr = bm + arow;
        au = make_uint4(0u, 0u, 0u, 0u);
        if (gr < M) au = *(const uint4*)(A + (size_t)gr * Kd + akb);
        if (!TRANSB) {
            int k2 = tid >> 5, c4 = (tid & 31) * 4;
            bv0 = *(const float4*)(B + (size_t)(2 * k2) * N + bn + c4);
            bv1 = *(const float4*)(B + (size_t)(2 * k2 + 1) * N + bn + c4);
        } else {
            int n0 = tid >> 2, kq0 = (tid & 3) * 4;
            int n1 = (tid + 256) >> 2, kq1 = ((tid + 256) & 3) * 4;
            bv0 = *(const float4*)(B + (size_t)(bn + n0) * Kd + kq0);
            bv1 = *(const float4*)(B + (size_t)(bn + n1) * Kd + kq1);
        }
    }
    // store tile 0 -> buf 0
    {
        int kb2 = akb >> 1;
        As[0][(kb2 + 0) * LDA + arow] = au.x;
        As[0][(kb2 + 1) * LDA + arow] = au.y;
        As[0][(kb2 + 2) * LDA + arow] = au.z;
        As[0][(kb2 + 3) * LDA + arow] = au.w;
        if (!TRANSB) {
            int k2 = tid >> 5, c4 = (tid & 31) * 4;
            uint4 u;
            u.x = f2h2(bv0.x, bv1.x); u.y = f2h2(bv0.y, bv1.y);
            u.z = f2h2(bv0.z, bv1.z); u.w = f2h2(bv0.w, bv1.w);
            *(uint4*)(&Bs[0][k2 * LDA + c4]) = u;
        } else {
            int n0 = tid >> 2, kq0 = (tid & 3) * 4;
            int n1 = (tid + 256) >> 2, kq1 = ((tid + 256) & 3) * 4;
            Bs[0][(kq0 / 2 + 0) * LDA + n0] = f2h2(bv0.x, bv0.y);
            Bs[0][(kq0 / 2 + 1) * LDA + n0] = f2h2(bv0.z, bv0.w);
            Bs[0][(kq1 / 2 + 0) * LDA + n1] = f2h2(bv1.x, bv1.y);
            Bs[0][(kq1 / 2 + 1) * LDA + n1] = f2h2(bv1.z, bv1.w);
        }
    }
    __syncthreads();

    for (int it = 0; it < nIter; it++) {
        int cur = it & 1;
        bool more = (it + 1 < nIter);
        // ---- prefetch next tile into registers ----
        if (more) {
            int k0 = (it + 1) * 16;
            int gr = bm + arow;
            au = make_uint4(0u, 0u, 0u, 0u);
            if (gr < M) au = *(const uint4*)(A + (size_t)gr * Kd + k0 + akb);
            if (!TRANSB) {
                int k2 = tid >> 5, c4 = (tid & 31) * 4;
                bv0 = *(const float4*)(B + (size_t)(k0 + 2 * k2) * N + bn + c4);
                bv1 = *(const float4*)(B + (size_t)(k0 + 2 * k2 + 1) * N + bn + c4);
            } else {
                int n0 = tid >> 2, kq0 = (tid & 3) * 4;
                int n1 = (tid + 256) >> 2, kq1 = ((tid + 256) & 3) * 4;
                bv0 = *(const float4*)(B + (size_t)(bn + n0) * Kd + k0 + kq0);
                bv1 = *(const float4*)(B + (size_t)(bn + n1) * Kd + k0 + kq1);
            }
        }
        // ---- mma on current buffer ----
        {
            uint32_t af[4][4], bf[4][2];
            #pragma unroll
            for (int mt = 0; mt < 4; mt++) {
                int rb = wm * 64 + mt * 16;
                af[mt][0] = As[cur][tid4 * LDA + rb + gid];
                af[mt][1] = As[cur][tid4 * LDA + rb + gid + 8];
                af[mt][2] = As[cur][(tid4 + 4) * LDA + rb + gid];
                af[mt][3] = As[cur][(tid4 + 4) * LDA + rb + gid + 8];
            }
            #pragma unroll
            for (int nt = 0; nt < 4; nt++) {
                int cb = wn * 32 + nt * 8;
                bf[nt][0] = Bs[cur][tid4 * LDA + cb + gid];
                bf[nt][1] = Bs[cur][(tid4 + 4) * LDA + cb + gid];
            }
            #pragma unroll
            for (int mt = 0; mt < 4; mt++)
                #pragma unroll
                for (int nt = 0; nt < 4; nt++)
                    mma_f16(d[mt][nt], af[mt], bf[nt]);
        }
        // ---- store next tile -> alternate buffer ----
        if (more) {
            int nxt = cur ^ 1;
            int kb2 = akb >> 1;
            As[nxt][(kb2 + 0) * LDA + arow] = au.x;
            As[nxt][(kb2 + 1) * LDA + arow] = au.y;
            As[nxt][(kb2 + 2) * LDA + arow] = au.z;
            As[nxt][(kb2 + 3) * LDA + arow] = au.w;
            if (!TRANSB) {
                int k2 = tid >> 5, c4 = (tid & 31) * 4;
                uint4 u;
                u.x = f2h2(bv0.x, bv1.x); u.y = f2h2(bv0.y, bv1.y);
                u.z = f2h2(bv0.z, bv1.z); u.w = f2h2(bv0.w, bv1.w);
                *(uint4*)(&Bs[nxt][k2 * LDA + c4]) = u;
            } else {
                int n0 = tid >> 2, kq0 = (tid & 3) * 4;
                int n1 = (tid + 256) >> 2, kq1 = ((tid + 256) & 3) * 4;
                Bs[nxt][(kq0 / 2 + 0) * LDA + n0] = f2h2(bv0.x, bv0.y);
                Bs[nxt][(kq0 / 2 + 1) * LDA + n0] = f2h2(bv0.z, bv0.w);
                Bs[nxt][(kq1 / 2 + 0) * LDA + n1] = f2h2(bv1.x, bv1.y);
                Bs[nxt][(kq1 / 2 + 1) * LDA + n1] = f2h2(bv1.z, bv1.w);
            }
            __syncthreads();
        }
    }
    // ---- epilogue ----
    #pragma unroll
    for (int mt = 0; mt < 4; mt++) {
        int r0 = bm + wm * 64 + mt * 16 + gid;
        int r1 = r0 + 8;
        #pragma unroll
        for (int nt = 0; nt < 4; nt++) {
            int cc = bn + wn * 32 + nt * 8 + tid4 * 2;
            float b0 = bias ? bias[cc] : 0.f;
            float b1 = bias ? bias[cc + 1] : 0.f;
            if (r0 < M) {
                float v0 = d[mt][nt][0] + b0, v1 = d[mt][nt][1] + b1;
                if (sizeof(OUTT) == 2) {
                    *(__half2*)((__half*)C + (size_t)r0 * N + cc) = __floats2half2_rn(v0, v1);
                } else {
                    *(float2*)((float*)C + (size_t)r0 * N + cc) = make_float2(v0, v1);
                }
            }
            if (r1 < M) {
                float v0 = d[mt][nt][2] + b0, v1 = d[mt][nt][3] + b1;
                if (sizeof(OUTT) == 2) {
                    *(__half2*)((__half*)C + (size_t)r1 * N + cc) = __floats2half2_rn(v0, v1);
                } else {
                    *(float2*)((float*)C + (size_t)r1 * N + cc) = make_float2(v0, v1);
                }
            }
        }
    }
}

// ---------------- GRU elementwise + relu + LN + build cat (fp16 in/out) ----------------
__global__ void k_gru(const __half* __restrict__ gi, const __half* __restrict__ gh,
                      const float* __restrict__ nf, const float* __restrict__ g_ln,
                      const float* __restrict__ b_ln, const float* __restrict__ kfeat,
                      __half* __restrict__ cath) {
    int v = blockIdx.x;
    int o = threadIdx.x;  // 256
    size_t b3 = (size_t)v * (3 * Dg);
    float ir = __half2float(gi[b3 + o]);
    float iz = __half2float(gi[b3 + Dg + o]);
    float inn = __half2float(gi[b3 + 2 * Dg + o]);
    float hr = __half2float(gh[b3 + o]);
    float hz = __half2float(gh[b3 + Dg + o]);
    float hn = __half2float(gh[b3 + 2 * Dg + o]);
    float x = nf[(size_t)v * Dg + o];
    float r = 1.f / (1.f + expf(-(ir + hr)));
    float z = 1.f / (1.f + expf(-(iz + hz)));
    float n = tanhf(inn + r * hn);
    float h = (1.f - z) * n + z * x;
    h = fmaxf(h, 0.f);
    float mu, rs;
    ln_stats_256(h, &mu, &rs);
    float g = (h - mu) * rs * g_ln[o] + b_ln[o];
    cath[(size_t)v * (Dg + OUTD) + o] = __float2half(g);
    cath[(size_t)v * (Dg + OUTD) + Dg + o] = __float2half(kfeat[(size_t)v * OUTD + o]);
}

// ---------------- final LN + relu (in place on d_out) ----------------
__global__ void k_outln(float* __restrict__ out, const float* __restrict__ gc,
                        const float* __restrict__ betac) {
    int v = blockIdx.x;
    int o = threadIdx.x;
    float y = out[(size_t)v * Dg + o];
    float mu, rs;
    ln_stats_256(y, &mu, &rs);
    out[(size_t)v * Dg + o] = fmaxf((y - mu) * rs * gc[o] + betac[o], 0.f);
}

// ---------------- launch ----------------
extern "C" void kernel_launch(void* const* d_in, const int* in_sizes, int n_in,
                              void* d_out, int out_size) {
    const float* nf    = (const float*)d_in[0];
    const int*   src   = (const int*)d_in[1];
    const int*   dst   = (const int*)d_in[2];
    const float* Wp    = (const float*)d_in[3];
    const float* bp    = (const float*)d_in[4];
    const float* gp    = (const float*)d_in[5];
    const float* betap = (const float*)d_in[6];
    const float* Wk    = (const float*)d_in[7];
    const float* bk    = (const float*)d_in[8];
    const float* gk    = (const float*)d_in[9];
    const float* betak = (const float*)d_in[10];
    const float* We    = (const float*)d_in[11];
    const float* be    = (const float*)d_in[12];
    const float* Wn    = (const float*)d_in[13];
    const float* bn    = (const float*)d_in[14];
    const float* W_ih  = (const float*)d_in[15];
    const float* W_hh  = (const float*)d_in[16];
    const float* b_ih  = (const float*)d_in[17];
    const float* b_hh  = (const float*)d_in[18];
    const float* g_ln  = (const float*)d_in[19];
    const float* b_ln  = (const float*)d_in[20];
    const float* Wc    = (const float*)d_in[21];
    const float* bc    = (const float*)d_in[22];
    const float* gc    = (const float*)d_in[23];
    const float* betac = (const float*)d_in[24];

    int V = in_sizes[0] / Dg;
    int E = in_sizes[1];
    float* out = (float*)d_out;

    float *npj, *Wkp, *ad, *as_, *att, *kf;
    __half *T, *hv, *gi, *gh, *npjh, *nfh, *ctxh, *cath;
    int *deg, *offs, *cursor, *eids, *bsums;
    cudaGetSymbolAddress((void**)&npj, g_npj);
    cudaGetSymbolAddress((void**)&npjh, g_npjh);
    cudaGetSymbolAddress((void**)&nfh, g_nfh);
    cudaGetSymbolAddress((void**)&Wkp, g_Wkp);
    cudaGetSymbolAddress((void**)&ad, g_ad);
    cudaGetSymbolAddress((void**)&as_, g_as);
    cudaGetSymbolAddress((void**)&hv, g_hv);
    cudaGetSymbolAddress((void**)&T, g_T);
    cudaGetSymbolAddress((void**)&att, g_att);
    cudaGetSymbolAddress((void**)&ctxh, g_ctxh);
    cudaGetSymbolAddress((void**)&kf, g_kf);
    cudaGetSymbolAddress((void**)&gi, g_gi);
    cudaGetSymbolAddress((void**)&gh, g_gh);
    cudaGetSymbolAddress((void**)&cath, g_cath);
    cudaGetSymbolAddress((void**)&deg, g_deg);
    cudaGetSymbolAddress((void**)&offs, g_offs);
    cudaGetSymbolAddress((void**)&cursor, g_cursor);
    cudaGetSymbolAddress((void**)&eids, g_eids);
    cudaGetSymbolAddress((void**)&bsums, g_bsums);

    cudaMemsetAsync(deg, 0, (size_t)V * sizeof(int));

    int nb_npj = (V + 7) / 8;
    int nb_wkp = (KPAD * Kp * OUTD) / 256;
    int nb_scan = (V + 255) / 256;

    // 1: fused preamble (npj+npjh || Wkp || hist || nf->fp16)
    k_pre<<<nb_npj + nb_wkp + HIST_BLOCKS + NFC_BLOCKS, 256>>>(
        nf, Wp, bp, gp, betap, We, Wk, dst,
        npj, npjh, nfh, ad, as_, Wkp, deg, V, E);
    // 2-4: fast scan -> offs + cursor
    k_scan_part<<<nb_scan, 256>>>(deg, offs, bsums, V);
    k_scan_mid<<<1, 256>>>(bsums, nb_scan);
    k_scan_apply<<<nb_scan, 256>>>(offs, cursor, bsums, V, E);
    // 5: T = npjh @ W'  (fp16 A)
    {
        dim3 grid(Kp * OUTD / 128, (V + 127) / 128);
        hgemm<false, __half><<<grid, 256>>>(npjh, Wkp, nullptr, T, V, Kp * OUTD, KPAD);
    }
    // 6: scatter -> eids
    k_scatter<<<592, 256>>>(dst, cursor, eids, E);
    // 7: hv = nfh @ Wn + bn  (fp16 out)
    {
        dim3 grid(Dg / 128, (V + 127) / 128);
        hgemm<false, __half><<<grid, 256>>>(nfh, Wn, bn, hv, V, Dg, Dg);
    }
    // 8: gh = nfh @ W_hh^T + b_hh  (fp16 out)
    {
        dim3 grid(3 * Dg / 128, (V + 127) / 128);
        hgemm<true, __half><<<grid, 256>>>(nfh, W_hh, b_hh, gh, V, 3 * Dg, Dg);
    }
    // 9: fused edge kernel (attn || kron); ctx written fp16
    k_edge<<<nb_npj + V, 256>>>(src, eids, offs, npj, T, bk, gk, betak,
                                ad, as_, be, hv, att, ctxh, kf, V);
    // 10: gi = ctxh @ W_ih^T + b_ih  (fp16 A, fp16 out)
    {
        dim3 grid(3 * Dg / 128, (V + 127) / 128);
        hgemm<true, __half><<<grid, 256>>>(ctxh, W_ih, b_ih, gi, V, 3 * Dg, Dg);
    }
    // 11: GRU elementwise + LN + cat build (fp16 out)
    k_gru<<<V, 256>>>(gi, gh, nf, g_ln, b_ln, kf, cath);
    // 12: out = cath @ Wc + bc  (fp16 A, fp32 out)
    {
        dim3 grid(Dg / 128, (V + 127) / 128);
        hgemm<false, float><<<grid, 256>>>(cath, Wc, bc, out, V, Dg, Dg + OUTD);
    }
    // 13: final LN + relu
    k_outln<<<V, 256>>>(out, gc, betac);
}

// round 13
// speedup vs baseline: 1.4454x; 1.1530x over previous
#include <cuda_runtime.h>
#include <cuda_bf16.h>
#include <cuda_fp16.h>
#include <math.h>
#include <stdint.h>

// ---------------- problem constants ----------------
#define VMAX 50000
#define EMAX 600000
#define Dg   256
#define Kp   20     // kron projection dim
#define KPAD 32     // padded projection dim for tensor-core GEMM
#define OUTD 256

// ---------------- device scratch (static; no allocation allowed) ----------------
__device__ float  g_npj[(size_t)VMAX * KPAD];        // padded fp32 (kron shfl source)
__device__ __half g_npjh[(size_t)VMAX * KPAD];       // fp16 copy (T-GEMM A)
__device__ __half g_nfh[(size_t)VMAX * Dg];          // fp16 copy of node_feats (GEMM A)
__device__ float  g_Wkp[(size_t)KPAD * Kp * OUTD];   // W' = transposed Wk (a-major)
__device__ float  g_ad[VMAX];
__device__ float  g_as[VMAX];
__device__ __half g_hv[(size_t)VMAX * Dg];           // fp16
__device__ __half g_T[(size_t)VMAX * Kp * OUTD];     // 512 MB fp16, a-major [v][a*256+o]
__device__ int    g_deg[VMAX];
__device__ int    g_offs[VMAX + 1];
__device__ int    g_bsums[256];
__device__ int    g_cursor[VMAX];
__device__ int    g_eids[EMAX];
__device__ float  g_att[EMAX];
__device__ __half g_ctxh[(size_t)VMAX * Dg];         // fp16 (gi GEMM A)
__device__ float  g_kf[(size_t)VMAX * OUTD];
__device__ __half g_gi[(size_t)VMAX * 3 * Dg];       // fp16
__device__ __half g_gh[(size_t)VMAX * 3 * Dg];       // fp16
__device__ __half g_cath[(size_t)VMAX * (Dg + OUTD)];// fp16 (final GEMM A)

// ---------------- helpers ----------------
__device__ __forceinline__ float warp_sum(float v) {
    #pragma unroll
    for (int o = 16; o; o >>= 1) v += __shfl_xor_sync(0xffffffffu, v, o);
    return v;
}
__device__ __forceinline__ float warp_max(float v) {
    #pragma unroll
    for (int o = 16; o; o >>= 1) v = fmaxf(v, __shfl_xor_sync(0xffffffffu, v, o));
    return v;
}
__device__ __forceinline__ uint32_t f2h2(float a, float b) {
    __half2 h = __floats2half2_rn(a, b);
    return *(uint32_t*)&h;
}
__device__ __forceinline__ void mma_f16(float* d, const uint32_t* a, const uint32_t* b) {
    asm volatile(
        "mma.sync.aligned.m16n8k16.row.col.f32.f16.f16.f32 "
        "{%0,%1,%2,%3}, {%4,%5,%6,%7}, {%8,%9}, {%0,%1,%2,%3};\n"
        : "+f"(d[0]), "+f"(d[1]), "+f"(d[2]), "+f"(d[3])
        : "r"(a[0]), "r"(a[1]), "r"(a[2]), "r"(a[3]), "r"(b[0]), "r"(b[1]));
}

// block (256 thr) LN stats over one value per thread
__device__ __forceinline__ void ln_stats_256(float v, float* mu, float* rs) {
    __shared__ float s1[8], s2[8];
    float a = v, b = v * v;
    a = warp_sum(a); b = warp_sum(b);
    int w = threadIdx.x >> 5, l = threadIdx.x & 31;
    if (l == 0) { s1[w] = a; s2[w] = b; }
    __syncthreads();
    if (w == 0) {
        a = (l < 8) ? s1[l] : 0.f;
        b = (l < 8) ? s2[l] : 0.f;
        #pragma unroll
        for (int o = 4; o; o >>= 1) { a += __shfl_xor_sync(0xffffffffu, a, o); b += __shfl_xor_sync(0xffffffffu, b, o); }
        if (l == 0) { s1[0] = a; s2[0] = b; }
    }
    __syncthreads();
    float m = s1[0] * (1.f / 256.f);
    float var = s2[0] * (1.f / 256.f) - m * m;
    *mu = m;
    *rs = rsqrtf(var + 1e-5f);
}

// ---------------- fused preamble: npj || Wkp || hist || nf->fp16 ----------------
#define HIST_BLOCKS 592
#define NFC_BLOCKS  800
__global__ void __launch_bounds__(256)
k_pre(const float* __restrict__ nf, const float* __restrict__ Wp,
      const float* __restrict__ bp, const float* __restrict__ gp,
      const float* __restrict__ betap, const float* __restrict__ We,
      const float* __restrict__ Wk, const int* __restrict__ dst,
      float* npj, __half* npjh, __half* nfh, float* ad, float* as_,
      float* Wkp, int* deg, int V, int E) {
    int nb_npj = (V + 7) / 8;
    int nb_wkp = (KPAD * Kp * OUTD) / 256;   // 640
    int bid = blockIdx.x;
    if (bid < nb_npj) {
        int warp = bid * 8 + (threadIdx.x >> 5);
        int lane = threadIdx.x & 31;
        if (warp >= V) return;
        const float* x = nf + (size_t)warp * Dg;
        float xr[8];
        #pragma unroll
        for (int j = 0; j < 8; j++) xr[j] = x[j * 32 + lane];
        float pa = 0.f, pb = 0.f;
        #pragma unroll
        for (int j = 0; j < 8; j++) { int i = j * 32 + lane; pa += xr[j] * We[i]; pb += xr[j] * We[Dg + i]; }
        pa = warp_sum(pa); pb = warp_sum(pb);
        if (lane == 0) { ad[warp] = pa; as_[warp] = pb; }
        float val = 0.f;
        for (int k = 0; k < Kp; k++) {
            float p = 0.f;
            #pragma unroll
            for (int j = 0; j < 8; j++) { int i = j * 32 + lane; p += xr[j] * Wp[i * Kp + k]; }
            p = warp_sum(p);
            p += bp[k];
            if (lane == k) val = p;
        }
        float c = (lane < Kp) ? val : 0.f;
        float s = warp_sum(c);
        float s2 = warp_sum(c * c);
        float mu = s / (float)Kp;
        float var = s2 / (float)Kp - mu * mu;
        float rs = rsqrtf(var + 1e-5f);
        float y = (lane < Kp) ? fmaxf((val - mu) * rs * gp[lane] + betap[lane], 0.f) : 0.f;
        npj[(size_t)warp * KPAD + lane] = y;
        npjh[(size_t)warp * KPAD + lane] = __float2half(y);
    } else if (bid < nb_npj + nb_wkp) {
        // a-major: Wkp[k][a*256+o] = Wk[(a*20+k)*256 + o]
        int idx = (bid - nb_npj) * 256 + threadIdx.x;
        int k = idx / (Kp * OUTD);
        int n = idx % (Kp * OUTD);
        int a = n / OUTD, o = n % OUTD;
        Wkp[idx] = (k < Kp) ? Wk[(size_t)(a * Kp + k) * OUTD + o] : 0.f;
    } else if (bid < nb_npj + nb_wkp + HIST_BLOCKS) {
        int vb = bid - nb_npj - nb_wkp;
        int stride = HIST_BLOCKS * 256;
        for (int i = vb * 256 + threadIdx.x; i < E; i += stride)
            atomicAdd(&deg[dst[i]], 1);
    } else {
        // nf -> fp16 (pairs)
        int cb = bid - nb_npj - nb_wkp - HIST_BLOCKS;
        size_t total = (size_t)V * Dg / 2;
        const float2* src2 = (const float2*)nf;
        __half2* dst2 = (__half2*)nfh;
        for (size_t i = (size_t)cb * 256 + threadIdx.x; i < total; i += (size_t)NFC_BLOCKS * 256)
            dst2[i] = __floats2half2_rn(src2[i].x, src2[i].y);
    }
}

// ---------------- fast 3-phase exclusive scan ----------------
__global__ void k_scan_part(const int* __restrict__ deg, int* offs, int* bsums, int V) {
    __shared__ int ws[8];
    int tid = threadIdx.x;
    int idx = blockIdx.x * 256 + tid;
    int v = (idx < V) ? deg[idx] : 0;
    int lane = tid & 31, w = tid >> 5;
    int x = v;
    #pragma unroll
    for (int o = 1; o < 32; o <<= 1) { int y = __shfl_up_sync(0xffffffffu, x, o); if (lane >= o) x += y; }
    if (lane == 31) ws[w] = x;
    __syncthreads();
    if (w == 0) {
        int s = (lane < 8) ? ws[lane] : 0;
        #pragma unroll
        for (int o = 1; o < 8; o <<= 1) { int y = __shfl_up_sync(0xffffffffu, s, o); if (lane >= o) s += y; }
        if (lane < 8) ws[lane] = s;
    }
    __syncthreads();
    int base = (w > 0) ? ws[w - 1] : 0;
    if (idx < V) offs[idx] = base + x - v;
    if (tid == 255) bsums[blockIdx.x] = base + x;
}
__global__ void k_scan_mid(int* bsums, int nb) {
    __shared__ int ws[8];
    int tid = threadIdx.x;
    int v = (tid < nb) ? bsums[tid] : 0;
    int lane = tid & 31, w = tid >> 5;
    int x = v;
    #pragma unroll
    for (int o = 1; o < 32; o <<= 1) { int y = __shfl_up_sync(0xffffffffu, x, o); if (lane >= o) x += y; }
    if (lane == 31) ws[w] = x;
    __syncthreads();
    if (w == 0) {
        int s = (lane < 8) ? ws[lane] : 0;
        #pragma unroll
        for (int o = 1; o < 8; o <<= 1) { int y = __shfl_up_sync(0xffffffffu, s, o); if (lane >= o) s += y; }
        if (lane < 8) ws[lane] = s;
    }
    __syncthreads();
    int base = (w > 0) ? ws[w - 1] : 0;
    if (tid < nb) bsums[tid] = base + x - v;
}
__global__ void k_scan_apply(int* offs, int* cursor, const int* __restrict__ bsums, int V, int E) {
    int idx = blockIdx.x * 256 + threadIdx.x;
    if (idx < V) {
        int o = offs[idx] + bsums[blockIdx.x];
        offs[idx] = o;
        cursor[idx] = o;
    }
    if (idx == 0) offs[V] = E;
}

__global__ void k_scatter(const int* __restrict__ dst, int* cursor, int* eids, int E) {
    for (int i = blockIdx.x * blockDim.x + threadIdx.x; i < E; i += gridDim.x * blockDim.x) {
        int p = atomicAdd(&cursor[dst[i]], 1);
        eids[p] = i;
    }
}

// ---------------- fused edge kernel: attn (gather) || kron (2 edges/warp pass) ----------------
__global__ void __launch_bounds__(256)
k_edge(const int* __restrict__ src, const int* __restrict__ eids,
       const int* __restrict__ offs, const float* __restrict__ npj,
       const __half* __restrict__ T, const float* __restrict__ bk,
       const float* __restrict__ gk, const float* __restrict__ betak,
       const float* __restrict__ ad, const float* __restrict__ as_,
       const float* __restrict__ be, const __half* __restrict__ hv,
       float* __restrict__ att, __half* __restrict__ ctxh,
       float* __restrict__ kf, int V) {
    __shared__ float Tsh[Kp * OUTD];
    __shared__ float bks[OUTD], gks[OUTD], bes[OUTD];
    __shared__ float kfs[OUTD];
    int nb_attn = (V + 7) / 8;
    int bid = blockIdx.x;
    int tid = threadIdx.x;
    int lane = tid & 31, w = tid >> 5;

    if (bid < nb_attn) {
        // ================= attention + context =================
        int node = bid * 8 + w;
        if (node >= V) return;
        int e0 = offs[node], e1 = offs[node + 1];
        float b = be[0];
        float advv = ad[node];
        float mx = -1e30f;
        for (int i = e0 + lane; i < e1; i += 32) {
            int e = eids[i];
            float lg = fmaxf(advv + as_[src[e]] + b, 0.f);
            att[i] = lg;
            mx = fmaxf(mx, lg);
        }
        mx = warp_max(mx);
        float sm = 0.f;
        for (int i = e0 + lane; i < e1; i += 32) {
            float ex = expf(att[i] - mx);
            att[i] = ex;
            sm += ex;
        }
        sm = warp_sum(sm);
        float inv = (sm > 0.f) ? 1.f / sm : 0.f;
        float c[8];
        #pragma unroll
        for (int j = 0; j < 8; j++) c[j] = 0.f;
        int nw = 0; float ww = 0.f;
        if (e0 < e1) { nw = src[eids[e0]]; ww = att[e0] * inv; }
        for (int i = e0; i < e1; i++) {
            int cs = nw; float cw = ww;
            if (i + 1 < e1) { nw = src[eids[i + 1]]; ww = att[i + 1] * inv; }
            const uint4* hp = (const uint4*)(hv + (size_t)cs * Dg) + lane;
            uint4 u = *hp;
            float2 f0 = __half22float2(*(__half2*)&u.x);
            float2 f1 = __half22float2(*(__half2*)&u.y);
            float2 f2 = __half22float2(*(__half2*)&u.z);
            float2 f3 = __half22float2(*(__half2*)&u.w);
            c[0] = fmaf(cw, f0.x, c[0]); c[1] = fmaf(cw, f0.y, c[1]);
            c[2] = fmaf(cw, f1.x, c[2]); c[3] = fmaf(cw, f1.y, c[3]);
            c[4] = fmaf(cw, f2.x, c[4]); c[5] = fmaf(cw, f2.y, c[5]);
            c[6] = fmaf(cw, f3.x, c[6]); c[7] = fmaf(cw, f3.y, c[7]);
        }
        uint4 o;
        o.x = f2h2(fmaxf(c[0], 0.f), fmaxf(c[1], 0.f));
        o.y = f2h2(fmaxf(c[2], 0.f), fmaxf(c[3], 0.f));
        o.z = f2h2(fmaxf(c[4], 0.f), fmaxf(c[5], 0.f));
        o.w = f2h2(fmaxf(c[6], 0.f), fmaxf(c[7], 0.f));
        *((uint4*)(ctxh + (size_t)node * Dg) + lane) = o;
        return;
    }

    // ================= kron branch: 2 edges per warp pass, stride 16 =================
    int d = bid - nb_attn;
    const __half2* Tg = (const __half2*)(T + (size_t)d * (Kp * OUTD));
    #pragma unroll
    for (int i = 0; i < Kp * OUTD / 2 / 256; i++) {
        int idx = i * 256 + tid;
        float2 f = __half22float2(Tg[idx]);
        Tsh[2 * idx] = f.x;
        Tsh[2 * idx + 1] = f.y;
    }
    bks[tid] = bk[tid];
    gks[tid] = gk[tid];
    bes[tid] = betak[tid];
    kfs[tid] = 0.f;
    __syncthreads();
    int e0 = offs[d], e1 = offs[d + 1];
    float kacc[8];
    #pragma unroll
    for (int j = 0; j < 8; j++) kacc[j] = 0.f;

    for (int base = e0 + w * 2; base < e1; base += 16) {
        int ne = e1 - base; if (ne > 2) ne = 2;
        float pv0 = 0.f, pv1 = 0.f;
        if (lane < Kp) {
            { int s = src[eids[base]]; pv0 = npj[(size_t)s * KPAD + lane]; }
            if (ne > 1) { int s = src[eids[base + 1]]; pv1 = npj[(size_t)s * KPAD + lane]; }
        }
        float y[2][8];
        #pragma unroll
        for (int j = 0; j < 8; j++) {
            float b = bks[j * 32 + lane];
            y[0][j] = b; y[1][j] = b;
        }
        #pragma unroll
        for (int a = 0; a < Kp; a++) {
            float p0 = __shfl_sync(0xffffffffu, pv0, a);
            float p1 = __shfl_sync(0xffffffffu, pv1, a);
            #pragma unroll
            for (int j = 0; j < 8; j++) {
                float tv = Tsh[a * OUTD + j * 32 + lane];
                y[0][j] = fmaf(p0, tv, y[0][j]);
                y[1][j] = fmaf(p1, tv, y[1][j]);
            }
        }
        #pragma unroll
        for (int t = 0; t < 2; t++) {
            if (t < ne) {
                float sA = 0.f, sB = 0.f;
                #pragma unroll
                for (int j = 0; j < 8; j++) { sA += y[t][j]; sB += y[t][j] * y[t][j]; }
                sA = warp_sum(sA); sB = warp_sum(sB);
                float mu = sA * (1.f / 256.f);
                float rs = rsqrtf(sB * (1.f / 256.f) - mu * mu + 1e-5f);
                #pragma unroll
                for (int j = 0; j < 8; j++) {
                    int o = j * 32 + lane;
                    kacc[j] += fmaxf((y[t][j] - mu) * rs * gks[o] + bes[o], 0.f);
                }
            }
        }
    }
    #pragma unroll
    for (int j = 0; j < 8; j++) atomicAdd(&kfs[j * 32 + lane], kacc[j]);
    __syncthreads();
    kf[(size_t)d * OUTD + tid] = kfs[tid];
}

// ---------------- fp16-A tensor-core GEMM, 2-stage double-buffered ----------------
// A is fp16 [M, Kd] row-major. B is fp32 weights (converted on staging).
template <bool TRANSB, typename OUTT>
__global__ void __launch_bounds__(256, 2)
hgemm(const __half* __restrict__ A, const float* __restrict__ B,
      const float* __restrict__ bias, OUTT* __restrict__ C,
      int M, int N, int Kd) {
    const int LDA = 136;
    __shared__ uint32_t As[2][8 * LDA];
    __shared__ uint32_t Bs[2][8 * LDA];
    int tid = threadIdx.x;
    int lane = tid & 31, w = tid >> 5;
    int gid = lane >> 2, tid4 = lane & 3;
    int wm = w & 1, wn = w >> 1;
    int bm = blockIdx.y * 128, bn = blockIdx.x * 128;

    float d[4][4][4];
    #pragma unroll
    for (int i = 0; i < 4; i++)
        #pragma unroll
        for (int j = 0; j < 4; j++)
            #pragma unroll
            for (int q = 0; q < 4; q++) d[i][j][q] = 0.f;

    int arow = tid >> 1, akb = (tid & 1) * 8;   // 8 halfs = 16B
    int nIter = Kd / 16;

    uint4 au;
    float4 bv0, bv1;
    {
        int gr = bm + arow;
        au = make_uint4(0u, 0u, 0u, 0u);
        if (gr < M) au = *(const uint4*)(A + (size_t)gr * Kd + akb);
        if (!TRANSB) {
            int k2 = tid >> 5, c4 = (tid & 31) * 4;
            bv0 = *(const float4*)(B + (size_t)(2 * k2) * N + bn + c4);
            bv1 = *(const float4*)(B + (size_t)(2 * k2 + 1) * N + bn + c4);
        } else {
            int n0 = tid >> 2, kq0 = (tid & 3) * 4;
            int n1 = (tid + 256) >> 2, kq1 = ((tid + 256) & 3) * 4;
            bv0 = *(const float4*)(B + (size_t)(bn + n0) * Kd + kq0);
            bv1 = *(const float4*)(B + (size_t)(bn + n1) * Kd + kq1);
        }
    }
    {
        int kb2 = akb >> 1;
        As[0][(kb2 + 0) * LDA + arow] = au.x;
        As[0][(kb2 + 1) * LDA + arow] = au.y;
        As[0][(kb2 + 2) * LDA + arow] = au.z;
        As[0][(kb2 + 3) * LDA + arow] = au.w;
        if (!TRANSB) {
            int k2 = tid >> 5, c4 = (tid & 31) * 4;
            uint4 u;
            u.x = f2h2(bv0.x, bv1.x); u.y = f2h2(bv0.y, bv1.y);
            u.z = f2h2(bv0.z, bv1.z); u.w = f2h2(bv0.w, bv1.w);
            *(uint4*)(&Bs[0][k2 * LDA + c4]) = u;
        } else {
            int n0 = tid >> 2, kq0 = (tid & 3) * 4;
            int n1 = (tid + 256) >> 2, kq1 = ((tid + 256) & 3) * 4;
            Bs[0][(kq0 / 2 + 0) * LDA + n0] = f2h2(bv0.x, bv0.y);
            Bs[0][(kq0 / 2 + 1) * LDA + n0] = f2h2(bv0.z, bv0.w);
            Bs[0][(kq1 / 2 + 0) * LDA + n1] = f2h2(bv1.x, bv1.y);
            Bs[0][(kq1 / 2 + 1) * LDA + n1] = f2h2(bv1.z, bv1.w);
        }
    }
    __syncthreads();

    for (int it = 0; it < nIter; it++) {
        int cur = it & 1;
        bool more = (it + 1 < nIter);
        if (more) {
            int k0 = (it + 1) * 16;
            int gr = bm + arow;
            au = make_uint4(0u, 0u, 0u, 0u);
            if (gr < M) au = *(const uint4*)(A + (size_t)gr * Kd + k0 + akb);
            if (!TRANSB) {
                int k2 = tid >> 5, c4 = (tid & 31) * 4;
                bv0 = *(const float4*)(B + (size_t)(k0 + 2 * k2) * N + bn + c4);
                bv1 = *(const float4*)(B + (size_t)(k0 + 2 * k2 + 1) * N + bn + c4);
            } else {
                int n0 = tid >> 2, kq0 = (tid & 3) * 4;
                int n1 = (tid + 256) >> 2, kq1 = ((tid + 256) & 3) * 4;
                bv0 = *(const float4*)(B + (size_t)(bn + n0) * Kd + k0 + kq0);
                bv1 = *(const float4*)(B + (size_t)(bn + n1) * Kd + k0 + kq1);
            }
        }
        {
            uint32_t af[4][4], bf[4][2];
            #pragma unroll
            for (int mt = 0; mt < 4; mt++) {
                int rb = wm * 64 + mt * 16;
                af[mt][0] = As[cur][tid4 * LDA + rb + gid];
                af[mt][1] = As[cur][tid4 * LDA + rb + gid + 8];
                af[mt][2] = As[cur][(tid4 + 4) * LDA + rb + gid];
                af[mt][3] = As[cur][(tid4 + 4) * LDA + rb + gid + 8];
            }
            #pragma unroll
            for (int nt = 0; nt < 4; nt++) {
                int cb = wn * 32 + nt * 8;
                bf[nt][0] = Bs[cur][tid4 * LDA + cb + gid];
                bf[nt][1] = Bs[cur][(tid4 + 4) * LDA + cb + gid];
            }
            #pragma unroll
            for (int mt = 0; mt < 4; mt++)
                #pragma unroll
                for (int nt = 0; nt < 4; nt++)
                    mma_f16(d[mt][nt], af[mt], bf[nt]);
        }
        if (more) {
            int nxt = cur ^ 1;
            int kb2 = akb >> 1;
            As[nxt][(kb2 + 0) * LDA + arow] = au.x;
            As[nxt][(kb2 + 1) * LDA + arow] = au.y;
            As[nxt][(kb2 + 2) * LDA + arow] = au.z;
            As[nxt][(kb2 + 3) * LDA + arow] = au.w;
            if (!TRANSB) {
                int k2 = tid >> 5, c4 = (tid & 31) * 4;
                uint4 u;
                u.x = f2h2(bv0.x, bv1.x); u.y = f2h2(bv0.y, bv1.y);
                u.z = f2h2(bv0.z, bv1.z); u.w = f2h2(bv0.w, bv1.w);
                *(uint4*)(&Bs[nxt][k2 * LDA + c4]) = u;
            } else {
                int n0 = tid >> 2, kq0 = (tid & 3) * 4;
                int n1 = (tid + 256) >> 2, kq1 = ((tid + 256) & 3) * 4;
                Bs[nxt][(kq0 / 2 + 0) * LDA + n0] = f2h2(bv0.x, bv0.y);
                Bs[nxt][(kq0 / 2 + 1) * LDA + n0] = f2h2(bv0.z, bv0.w);
                Bs[nxt][(kq1 / 2 + 0) * LDA + n1] = f2h2(bv1.x, bv1.y);
                Bs[nxt][(kq1 / 2 + 1) * LDA + n1] = f2h2(bv1.z, bv1.w);
            }
            __syncthreads();
        }
    }
    #pragma unroll
    for (int mt = 0; mt < 4; mt++) {
        int r0 = bm + wm * 64 + mt * 16 + gid;
        int r1 = r0 + 8;
        #pragma unroll
        for (int nt = 0; nt < 4; nt++) {
            int cc = bn + wn * 32 + nt * 8 + tid4 * 2;
            float b0 = bias ? bias[cc] : 0.f;
            float b1 = bias ? bias[cc + 1] : 0.f;
            if (r0 < M) {
                float v0 = d[mt][nt][0] + b0, v1 = d[mt][nt][1] + b1;
                if (sizeof(OUTT) == 2) {
                    *(__half2*)((__half*)C + (size_t)r0 * N + cc) = __floats2half2_rn(v0, v1);
                } else {
                    *(float2*)((float*)C + (size_t)r0 * N + cc) = make_float2(v0, v1);
                }
            }
            if (r1 < M) {
                float v0 = d[mt][nt][2] + b0, v1 = d[mt][nt][3] + b1;
                if (sizeof(OUTT) == 2) {
                    *(__half2*)((__half*)C + (size_t)r1 * N + cc) = __floats2half2_rn(v0, v1);
                } else {
                    *(float2*)((float*)C + (size_t)r1 * N + cc) = make_float2(v0, v1);
                }
            }
        }
    }
}

// ---------------- GRU elementwise + relu + LN + build cat (fp16 in/out) ----------------
__global__ void k_gru(const __half* __restrict__ gi, const __half* __restrict__ gh,
                      const float* __restrict__ nf, const float* __restrict__ g_ln,
                      const float* __restrict__ b_ln, const float* __restrict__ kfeat,
                      __half* __restrict__ cath) {
    int v = blockIdx.x;
    int o = threadIdx.x;  // 256
    size_t b3 = (size_t)v * (3 * Dg);
    float ir = __half2float(gi[b3 + o]);
    float iz = __half2float(gi[b3 + Dg + o]);
    float inn = __half2float(gi[b3 + 2 * Dg + o]);
    float hr = __half2float(gh[b3 + o]);
    float hz = __half2float(gh[b3 + Dg + o]);
    float hn = __half2float(gh[b3 + 2 * Dg + o]);
    float x = nf[(size_t)v * Dg + o];
    float r = 1.f / (1.f + expf(-(ir + hr)));
    float z = 1.f / (1.f + expf(-(iz + hz)));
    float n = tanhf(inn + r * hn);
    float h = (1.f - z) * n + z * x;
    h = fmaxf(h, 0.f);
    float mu, rs;
    ln_stats_256(h, &mu, &rs);
    float g = (h - mu) * rs * g_ln[o] + b_ln[o];
    cath[(size_t)v * (Dg + OUTD) + o] = __float2half(g);
    cath[(size_t)v * (Dg + OUTD) + Dg + o] = __float2half(kfeat[(size_t)v * OUTD + o]);
}

// ---------------- final LN + relu (in place on d_out) ----------------
__global__ void k_outln(float* __restrict__ out, const float* __restrict__ gc,
                        const float* __restrict__ betac) {
    int v = blockIdx.x;
    int o = threadIdx.x;
    float y = out[(size_t)v * Dg + o];
    float mu, rs;
    ln_stats_256(y, &mu, &rs);
    out[(size_t)v * Dg + o] = fmaxf((y - mu) * rs * gc[o] + betac[o], 0.f);
}

// ---------------- launch ----------------
extern "C" void kernel_launch(void* const* d_in, const int* in_sizes, int n_in,
                              void* d_out, int out_size) {
    const float* nf    = (const float*)d_in[0];
    const int*   src   = (const int*)d_in[1];
    const int*   dst   = (const int*)d_in[2];
    const float* Wp    = (const float*)d_in[3];
    const float* bp    = (const float*)d_in[4];
    const float* gp    = (const float*)d_in[5];
    const float* betap = (const float*)d_in[6];
    const float* Wk    = (const float*)d_in[7];
    const float* bk    = (const float*)d_in[8];
    const float* gk    = (const float*)d_in[9];
    const float* betak = (const float*)d_in[10];
    const float* We    = (const float*)d_in[11];
    const float* be    = (const float*)d_in[12];
    const float* Wn    = (const float*)d_in[13];
    const float* bn    = (const float*)d_in[14];
    const float* W_ih  = (const float*)d_in[15];
    const float* W_hh  = (const float*)d_in[16];
    const float* b_ih  = (const float*)d_in[17];
    const float* b_hh  = (const float*)d_in[18];
    const float* g_ln  = (const float*)d_in[19];
    const float* b_ln  = (const float*)d_in[20];
    const float* Wc    = (const float*)d_in[21];
    const float* bc    = (const float*)d_in[22];
    const float* gc    = (const float*)d_in[23];
    const float* betac = (const float*)d_in[24];

    int V = in_sizes[0] / Dg;
    int E = in_sizes[1];
    float* out = (float*)d_out;

    float *npj, *Wkp, *ad, *as_, *att, *kf;
    __half *T, *hv, *gi, *gh, *npjh, *nfh, *ctxh, *cath;
    int *deg, *offs, *cursor, *eids, *bsums;
    cudaGetSymbolAddress((void**)&npj, g_npj);
    cudaGetSymbolAddress((void**)&npjh, g_npjh);
    cudaGetSymbolAddress((void**)&nfh, g_nfh);
    cudaGetSymbolAddress((void**)&Wkp, g_Wkp);
    cudaGetSymbolAddress((void**)&ad, g_ad);
    cudaGetSymbolAddress((void**)&as_, g_as);
    cudaGetSymbolAddress((void**)&hv, g_hv);
    cudaGetSymbolAddress((void**)&T, g_T);
    cudaGetSymbolAddress((void**)&att, g_att);
    cudaGetSymbolAddress((void**)&ctxh, g_ctxh);
    cudaGetSymbolAddress((void**)&kf, g_kf);
    cudaGetSymbolAddress((void**)&gi, g_gi);
    cudaGetSymbolAddress((void**)&gh, g_gh);
    cudaGetSymbolAddress((void**)&cath, g_cath);
    cudaGetSymbolAddress((void**)&deg, g_deg);
    cudaGetSymbolAddress((void**)&offs, g_offs);
    cudaGetSymbolAddress((void**)&cursor, g_cursor);
    cudaGetSymbolAddress((void**)&eids, g_eids);
    cudaGetSymbolAddress((void**)&bsums, g_bsums);

    cudaMemsetAsync(deg, 0, (size_t)V * sizeof(int));

    int nb_npj = (V + 7) / 8;
    int nb_wkp = (KPAD * Kp * OUTD) / 256;
    int nb_scan = (V + 255) / 256;

    // 1: fused preamble (npj+npjh || Wkp || hist || nf->fp16)
    k_pre<<<nb_npj + nb_wkp + HIST_BLOCKS + NFC_BLOCKS, 256>>>(
        nf, Wp, bp, gp, betap, We, Wk, dst,
        npj, npjh, nfh, ad, as_, Wkp, deg, V, E);
    // 2-4: fast scan -> offs + cursor
    k_scan_part<<<nb_scan, 256>>>(deg, offs, bsums, V);
    k_scan_mid<<<1, 256>>>(bsums, nb_scan);
    k_scan_apply<<<nb_scan, 256>>>(offs, cursor, bsums, V, E);
    // 5: T = npjh @ W'  (fp16 A)
    {
        dim3 grid(Kp * OUTD / 128, (V + 127) / 128);
        hgemm<false, __half><<<grid, 256>>>(npjh, Wkp, nullptr, T, V, Kp * OUTD, KPAD);
    }
    // 6: scatter -> eids
    k_scatter<<<592, 256>>>(dst, cursor, eids, E);
    // 7: hv = nfh @ Wn + bn  (fp16 out)
    {
        dim3 grid(Dg / 128, (V + 127) / 128);
        hgemm<false, __half><<<grid, 256>>>(nfh, Wn, bn, hv, V, Dg, Dg);
    }
    // 8: gh = nfh @ W_hh^T + b_hh  (fp16 out)
    {
        dim3 grid(3 * Dg / 128, (V + 127) / 128);
        hgemm<true, __half><<<grid, 256>>>(nfh, W_hh, b_hh, gh, V, 3 * Dg, Dg);
    }
    // 9: fused edge kernel (attn || kron); ctx written fp16
    k_edge<<<nb_npj + V, 256>>>(src, eids, offs, npj, T, bk, gk, betak,
                                ad, as_, be, hv, att, ctxh, kf, V);
    // 10: gi = ctxh @ W_ih^T + b_ih  (fp16 A, fp16 out)
    {
        dim3 grid(3 * Dg / 128, (V + 127) / 128);
        hgemm<true, __half><<<grid, 256>>>(ctxh, W_ih, b_ih, gi, V, 3 * Dg, Dg);
    }
    // 11: GRU elementwise + LN + cat build (fp16 out)
    k_gru<<<V, 256>>>(gi, gh, nf, g_ln, b_ln, kf, cath);
    // 12: out = cath @ Wc + bc  (fp16 A, fp32 out)
    {
        dim3 grid(Dg / 128, (V + 127) / 128);
        hgemm<false, float><<<grid, 256>>>(cath, Wc, bc, out, V, Dg, Dg + OUTD);
    }
    // 13: final LN + relu
    k_outln<<<V, 256>>>(out, gc, betac);
}